// round 3
// baseline (speedup 1.0000x reference)
#include <cuda_runtime.h>
#include <cuda_bf16.h>
#include <math.h>

// Problem constants
#define BATCH 4
#define SEQ   1024
#define DMODEL 1024
#define HEADS 16
#define DK    64

// Scratch (device globals: allocation-free rule)
__device__ float g_Q[BATCH * HEADS * SEQ * DK];   // [b,h,n,d]
__device__ float g_K[BATCH * HEADS * SEQ * DK];
__device__ float g_V[BATCH * HEADS * SEQ * DK];
__device__ float g_O[BATCH * SEQ * DMODEL];       // [b,n,D] attention output

// ---------------------------------------------------------------------------
// SGEMM: out[M=4096, N=1024] = A[4096,1024] @ W[1024,1024] + bias
// BM=BN=128, BK=16, 256 threads, 8x8 per-thread tile.
// headInterleave=1 writes to [b,h,n,d] layout; 0 writes row-major [m,c].
// ---------------------------------------------------------------------------
#define GBM 128
#define GBN 128
#define GBK 16

__global__ __launch_bounds__(256, 2)
void sgemm_bias_kernel(const float* __restrict__ A,
                       const float* __restrict__ W,
                       const float* __restrict__ bias,
                       float* __restrict__ out,
                       int headInterleave)
{
    __shared__ float As[GBK][GBM + 4];   // stride 132 (16B-aligned rows)
    __shared__ float Bs[GBK][GBN];

    const int m0 = blockIdx.y * GBM;
    const int n0 = blockIdx.x * GBN;
    const int tid = threadIdx.x;
    const int ty = tid >> 4;    // 0..15
    const int tx = tid & 15;    // 0..15

    float acc[8][8];
#pragma unroll
    for (int i = 0; i < 8; i++)
#pragma unroll
        for (int j = 0; j < 8; j++) acc[i][j] = 0.0f;

    for (int k0 = 0; k0 < DMODEL; k0 += GBK) {
        // Load A tile (128x16) transposed into As[k][m]
#pragma unroll
        for (int q = 0; q < 2; q++) {
            int idx = tid * 2 + q;          // 0..511
            int row = idx >> 2;             // 0..127
            int ks  = (idx & 3) * 4;        // 0,4,8,12
            float4 v = *(const float4*)(A + (size_t)(m0 + row) * DMODEL + k0 + ks);
            As[ks + 0][row] = v.x;
            As[ks + 1][row] = v.y;
            As[ks + 2][row] = v.z;
            As[ks + 3][row] = v.w;
        }
        // Load B tile (16x128)
#pragma unroll
        for (int q = 0; q < 2; q++) {
            int idx = tid * 2 + q;          // 0..511
            int kk = idx >> 5;              // 0..15
            int cs = (idx & 31) * 4;        // 0..124
            *(float4*)&Bs[kk][cs] = *(const float4*)(W + (size_t)(k0 + kk) * DMODEL + n0 + cs);
        }
        __syncthreads();

#pragma unroll
        for (int kk = 0; kk < GBK; kk++) {
            float a[8], b[8];
            *(float4*)(a)     = *(float4*)&As[kk][ty * 4];
            *(float4*)(a + 4) = *(float4*)&As[kk][64 + ty * 4];
            *(float4*)(b)     = *(float4*)&Bs[kk][tx * 4];
            *(float4*)(b + 4) = *(float4*)&Bs[kk][64 + tx * 4];
#pragma unroll
            for (int i = 0; i < 8; i++)
#pragma unroll
                for (int j = 0; j < 8; j++)
                    acc[i][j] = fmaf(a[i], b[j], acc[i][j]);
        }
        __syncthreads();
    }

    // Epilogue
#pragma unroll
    for (int i = 0; i < 8; i++) {
        int mr = (i < 4) ? (ty * 4 + i) : (64 + ty * 4 + (i - 4));
        int m = m0 + mr;
#pragma unroll
        for (int j = 0; j < 8; j++) {
            int cr = (j < 4) ? (tx * 4 + j) : (64 + tx * 4 + (j - 4));
            int c = n0 + cr;
            float val = acc[i][j] + bias[c];
            if (headInterleave) {
                int b = m >> 10;        // m / SEQ
                int n = m & 1023;
                int h = c >> 6;         // c / DK
                int d = c & 63;
                out[(size_t)(b * HEADS + h) * (SEQ * DK) + (size_t)n * DK + d] = val;
            } else {
                out[(size_t)m * DMODEL + c] = val;
            }
        }
    }
}

// ---------------------------------------------------------------------------
// Fused flash attention with additive bias + key mask.
// Grid: (N/64, HEADS, BATCH). Block: 256 threads.
// Tiles: 64 queries x 64 keys, dk = 64. Online softmax.
// mask is read as 4-byte words (bool promoted to int32/float32 by the
// harness); nonzero == unmasked. This is correct for both encodings.
// ---------------------------------------------------------------------------
#define ASTRIDE 68
#define ATTN_SMEM_BYTES (4 * 64 * ASTRIDE * 4)

__global__ __launch_bounds__(256, 2)
void attn_kernel(const float* __restrict__ Bij,
                 const unsigned int* __restrict__ maskW)
{
    extern __shared__ float smem[];
    float* sQ  = smem;                  // [64][68]
    float* sK  = sQ  + 64 * ASTRIDE;    // [64][68]  (key-major: [key][d])
    float* sVt = sK  + 64 * ASTRIDE;    // [64][68]  (transposed: [d][key])
    float* sP  = sVt + 64 * ASTRIDE;    // [64][68]  bias tile, then probabilities
    __shared__ unsigned char sM[64];

    const int b  = blockIdx.z;
    const int h  = blockIdx.y;
    const int q0 = blockIdx.x * 64;
    const int tid = threadIdx.x;
    const int ty = tid >> 4;    // 0..15 -> rows 4*ty..4*ty+3
    const int tx = tid & 15;    // 0..15 -> cols 4*tx..4*tx+3
    const int bh = b * HEADS + h;
    const float scale = 0.125f; // 1/sqrt(64)

    // Load Q tile (coalesced)
    {
        const float* Qg = g_Q + (size_t)(bh * SEQ + q0) * DK;
        int r = tid >> 2, seg = tid & 3;
#pragma unroll
        for (int u = 0; u < 4; u++) {
            int c = seg * 16 + u * 4;
            *(float4*)&sQ[r * ASTRIDE + c] = *(const float4*)(Qg + r * DK + c);
        }
    }

    float mI[4], lI[4], acc[4][4];
#pragma unroll
    for (int i = 0; i < 4; i++) {
        mI[i] = -INFINITY; lI[i] = 0.0f;
#pragma unroll
        for (int j = 0; j < 4; j++) acc[i][j] = 0.0f;
    }

    for (int kt = 0; kt < SEQ / 64; kt++) {
        const int k0 = kt * 64;
        __syncthreads();   // previous PV reads complete before overwrite

        // Load K, V (transposed), bias tile — all coalesced from global
        {
            int r = tid >> 2, seg = tid & 3;
            const float* Kg = g_K + (size_t)(bh * SEQ + k0) * DK;
            const float* Vg = g_V + (size_t)(bh * SEQ + k0) * DK;
            const float* Bg = Bij + ((size_t)bh * SEQ + (q0 + r)) * SEQ + k0;
#pragma unroll
            for (int u = 0; u < 4; u++) {
                int c = seg * 16 + u * 4;
                *(float4*)&sK[r * ASTRIDE + c] = *(const float4*)(Kg + r * DK + c);
                float4 v = *(const float4*)(Vg + r * DK + c);
                sVt[(c + 0) * ASTRIDE + r] = v.x;
                sVt[(c + 1) * ASTRIDE + r] = v.y;
                sVt[(c + 2) * ASTRIDE + r] = v.z;
                sVt[(c + 3) * ASTRIDE + r] = v.w;
                *(float4*)&sP[r * ASTRIDE + c] = *(const float4*)(Bg + c);
            }
            // 4-byte reads: nonzero (int 1 or float 1.0f) == unmasked
            if (tid < 64) sM[tid] = (maskW[b * SEQ + k0 + tid] != 0u) ? 1 : 0;
        }
        __syncthreads();

        // S = Q K^T (4x4 frag per thread)
        float s[4][4];
#pragma unroll
        for (int i = 0; i < 4; i++)
#pragma unroll
            for (int j = 0; j < 4; j++) s[i][j] = 0.0f;

#pragma unroll
        for (int d = 0; d < 64; d += 4) {
            float4 qv[4], kv[4];
#pragma unroll
            for (int i = 0; i < 4; i++) qv[i] = *(float4*)&sQ[(4 * ty + i) * ASTRIDE + d];
#pragma unroll
            for (int j = 0; j < 4; j++) kv[j] = *(float4*)&sK[(4 * tx + j) * ASTRIDE + d];
#pragma unroll
            for (int i = 0; i < 4; i++)
#pragma unroll
                for (int j = 0; j < 4; j++) {
                    s[i][j] = fmaf(qv[i].x, kv[j].x, s[i][j]);
                    s[i][j] = fmaf(qv[i].y, kv[j].y, s[i][j]);
                    s[i][j] = fmaf(qv[i].z, kv[j].z, s[i][j]);
                    s[i][j] = fmaf(qv[i].w, kv[j].w, s[i][j]);
                }
        }

        // bias + mask + online softmax update; write p into sP (same cells we read)
#pragma unroll
        for (int i = 0; i < 4; i++) {
            int rI = 4 * ty + i;
            float sv[4];
#pragma unroll
            for (int j = 0; j < 4; j++) {
                int c = 4 * tx + j;
                float val = s[i][j] * scale + sP[rI * ASTRIDE + c];
                sv[j] = sM[c] ? val : -10000.0f;
            }
            float mx = fmaxf(fmaxf(sv[0], sv[1]), fmaxf(sv[2], sv[3]));
#pragma unroll
            for (int off = 8; off > 0; off >>= 1)
                mx = fmaxf(mx, __shfl_xor_sync(0xffffffffu, mx, off, 16));
            float mNew = fmaxf(mI[i], mx);
            float alpha = __expf(mI[i] - mNew);
            float rs = 0.0f;
#pragma unroll
            for (int j = 0; j < 4; j++) {
                float p = __expf(sv[j] - mNew);
                sP[rI * ASTRIDE + 4 * tx + j] = p;
                rs += p;
            }
#pragma unroll
            for (int off = 8; off > 0; off >>= 1)
                rs += __shfl_xor_sync(0xffffffffu, rs, off, 16);
            lI[i] = lI[i] * alpha + rs;
            mI[i] = mNew;
#pragma unroll
            for (int j = 0; j < 4; j++) acc[i][j] *= alpha;
        }
        __syncthreads();

        // O += P V  (V transposed in smem -> both operands float4 over key dim)
#pragma unroll
        for (int kk = 0; kk < 64; kk += 4) {
            float4 pv[4], vv[4];
#pragma unroll
            for (int i = 0; i < 4; i++) pv[i] = *(float4*)&sP[(4 * ty + i) * ASTRIDE + kk];
#pragma unroll
            for (int j = 0; j < 4; j++) vv[j] = *(float4*)&sVt[(4 * tx + j) * ASTRIDE + kk];
#pragma unroll
            for (int i = 0; i < 4; i++)
#pragma unroll
                for (int j = 0; j < 4; j++) {
                    acc[i][j] = fmaf(pv[i].x, vv[j].x, acc[i][j]);
                    acc[i][j] = fmaf(pv[i].y, vv[j].y, acc[i][j]);
                    acc[i][j] = fmaf(pv[i].z, vv[j].z, acc[i][j]);
                    acc[i][j] = fmaf(pv[i].w, vv[j].w, acc[i][j]);
                }
        }
    }

    // Epilogue: normalize and write [b, n, h*64+d]
    float* Og = g_O + ((size_t)b * SEQ + q0) * DMODEL + h * DK;
#pragma unroll
    for (int i = 0; i < 4; i++) {
        float inv = 1.0f / lI[i];
#pragma unroll
        for (int j = 0; j < 4; j++)
            Og[(size_t)(4 * ty + i) * DMODEL + 4 * tx + j] = acc[i][j] * inv;
    }
}

// ---------------------------------------------------------------------------
extern "C" void kernel_launch(void* const* d_in, const int* in_sizes, int n_in,
                              void* d_out, int out_size)
{
    // Identify inputs by element count (robust to metadata ordering):
    //   B_ij: 67108864, X: 4194304, mask: 4096, W*: 1048576 (x4), b*: 1024 (x4)
    const float* X = 0; const float* Bij = 0; const void* maskP = 0;
    const float* Ws[4] = {0, 0, 0, 0};
    const float* bs[4] = {0, 0, 0, 0};
    int nW = 0, nB = 0;
    for (int i = 0; i < n_in; i++) {
        int sz = in_sizes[i];
        if (sz == BATCH * HEADS * SEQ * SEQ)      Bij  = (const float*)d_in[i];
        else if (sz == BATCH * SEQ * DMODEL)      X    = (const float*)d_in[i];
        else if (sz == BATCH * SEQ)               maskP = d_in[i];
        else if (sz == DMODEL * DMODEL && nW < 4) Ws[nW++] = (const float*)d_in[i];
        else if (sz == DMODEL && nB < 4)          bs[nB++] = (const float*)d_in[i];
    }
    // Appearance order assumed q, k, v, o (reference signature order)
    const float *Wq = Ws[0], *Wk = Ws[1], *Wv = Ws[2], *Wo = Ws[3];
    const float *bq = bs[0], *bk = bs[1], *bv = bs[2], *bo = bs[3];
    float* out = (float*)d_out;

    float *qp, *kp, *vp, *op;
    cudaGetSymbolAddress((void**)&qp, g_Q);
    cudaGetSymbolAddress((void**)&kp, g_K);
    cudaGetSymbolAddress((void**)&vp, g_V);
    cudaGetSymbolAddress((void**)&op, g_O);

    cudaFuncSetAttribute(attn_kernel, cudaFuncAttributeMaxDynamicSharedMemorySize,
                         ATTN_SMEM_BYTES);

    dim3 gGemm(DMODEL / GBN, (BATCH * SEQ) / GBM);   // (8, 32)

    sgemm_bias_kernel<<<gGemm, 256>>>(X, Wq, bq, qp, 1);
    sgemm_bias_kernel<<<gGemm, 256>>>(X, Wk, bk, kp, 1);
    sgemm_bias_kernel<<<gGemm, 256>>>(X, Wv, bv, vp, 1);

    dim3 gAttn(SEQ / 64, HEADS, BATCH);              // (16, 16, 4)
    attn_kernel<<<gAttn, 256, ATTN_SMEM_BYTES>>>(Bij, (const unsigned int*)maskP);

    sgemm_bias_kernel<<<gGemm, 256>>>(op, Wo, bo, out, 0);
}

// round 4
// speedup vs baseline: 2.2093x; 2.2093x over previous
#include <cuda_runtime.h>
#include <cuda_bf16.h>
#include <math.h>

// Problem constants
#define BATCH 4
#define SEQ   1024
#define DMODEL 1024
#define HEADS 16
#define DK    64

// Scratch (device globals: allocation-free rule)
__device__ float g_Q[BATCH * HEADS * SEQ * DK];   // [b,h,n,d]
__device__ float g_K[BATCH * HEADS * SEQ * DK];
__device__ float g_V[BATCH * HEADS * SEQ * DK];
__device__ float g_O[BATCH * SEQ * DMODEL];       // [b,n,D] attention output

// ---------------------------------------------------------------------------
// tf32 helpers
// ---------------------------------------------------------------------------
__device__ __forceinline__ unsigned int f2tf32(float x) {
    unsigned int u;
    asm("cvt.rna.tf32.f32 %0, %1;" : "=r"(u) : "f"(x));
    return u;
}

__device__ __forceinline__ void mma_tf32(float c[4],
                                         unsigned int a0, unsigned int a1,
                                         unsigned int a2, unsigned int a3,
                                         unsigned int b0, unsigned int b1) {
    asm volatile(
        "mma.sync.aligned.m16n8k8.row.col.f32.tf32.tf32.f32 "
        "{%0,%1,%2,%3}, {%4,%5,%6,%7}, {%8,%9}, {%0,%1,%2,%3};\n"
        : "+f"(c[0]), "+f"(c[1]), "+f"(c[2]), "+f"(c[3])
        : "r"(a0), "r"(a1), "r"(a2), "r"(a3), "r"(b0), "r"(b1));
}

// ---------------------------------------------------------------------------
// tf32 tensor-core GEMM: out[4096,1024] = A[4096,1024] @ W[1024,1024] + bias
// BM=128, BN=128, BK=16. 256 threads = 8 warps (2x4). Warp tile 64x32.
// Per warp: 4 m-tiles (16) x 4 n-tiles (8), k in two steps of 8.
// As[128][20] m-major (frag banks 20*gid+tig: conflict-free)
// Bs[16][136] k-major (frag banks 8*tig+gid: conflict-free)
// ---------------------------------------------------------------------------
#define TBM 128
#define TBN 128
#define TBK 16
#define AST 20
#define BST 136

__global__ __launch_bounds__(256, 2)
void tf32_gemm_kernel(const float* __restrict__ A,
                      const float* __restrict__ W,
                      const float* __restrict__ bias,
                      float* __restrict__ out,
                      int headInterleave)
{
    __shared__ float As[TBM][AST];
    __shared__ float Bs[TBK][BST];

    const int m0 = blockIdx.y * TBM;
    const int n0 = blockIdx.x * TBN;
    const int tid = threadIdx.x;
    const int wid = tid >> 5;
    const int lane = tid & 31;
    const int wm = wid >> 2;          // 0..1
    const int wn = wid & 3;           // 0..3
    const int gid = lane >> 2;        // 0..7
    const int tig = lane & 3;         // 0..3

    float c[4][4][4];
#pragma unroll
    for (int i = 0; i < 4; i++)
#pragma unroll
        for (int j = 0; j < 4; j++)
#pragma unroll
            for (int r = 0; r < 4; r++) c[i][j][r] = 0.0f;

    for (int k0 = 0; k0 < DMODEL; k0 += TBK) {
        // A tile 128x16, row-major into As[m][k] (converted to tf32)
#pragma unroll
        for (int q = 0; q < 2; q++) {
            int idx = tid * 2 + q;          // 0..511
            int row = idx >> 2;             // 0..127
            int ks  = (idx & 3) * 4;        // 0,4,8,12
            float4 v = *(const float4*)(A + (size_t)(m0 + row) * DMODEL + k0 + ks);
            As[row][ks + 0] = __uint_as_float(f2tf32(v.x));
            As[row][ks + 1] = __uint_as_float(f2tf32(v.y));
            As[row][ks + 2] = __uint_as_float(f2tf32(v.z));
            As[row][ks + 3] = __uint_as_float(f2tf32(v.w));
        }
        // B tile 16x128 into Bs[k][n]
#pragma unroll
        for (int q = 0; q < 2; q++) {
            int idx = tid * 2 + q;          // 0..511
            int kk = idx >> 5;              // 0..15
            int cs = (idx & 31) * 4;        // 0..124
            float4 v = *(const float4*)(W + (size_t)(k0 + kk) * DMODEL + n0 + cs);
            Bs[kk][cs + 0] = __uint_as_float(f2tf32(v.x));
            Bs[kk][cs + 1] = __uint_as_float(f2tf32(v.y));
            Bs[kk][cs + 2] = __uint_as_float(f2tf32(v.z));
            Bs[kk][cs + 3] = __uint_as_float(f2tf32(v.w));
        }
        __syncthreads();

#pragma unroll
        for (int ks = 0; ks < 2; ks++) {
            const int kb = ks * 8;
            unsigned int af[4][4], bf[4][2];
#pragma unroll
            for (int i = 0; i < 4; i++) {
                int mb = wm * 64 + i * 16;
                af[i][0] = __float_as_uint(As[mb + gid    ][kb + tig]);
                af[i][1] = __float_as_uint(As[mb + gid + 8][kb + tig]);
                af[i][2] = __float_as_uint(As[mb + gid    ][kb + tig + 4]);
                af[i][3] = __float_as_uint(As[mb + gid + 8][kb + tig + 4]);
            }
#pragma unroll
            for (int j = 0; j < 4; j++) {
                int nb = wn * 32 + j * 8;
                bf[j][0] = __float_as_uint(Bs[kb + tig    ][nb + gid]);
                bf[j][1] = __float_as_uint(Bs[kb + tig + 4][nb + gid]);
            }
#pragma unroll
            for (int i = 0; i < 4; i++)
#pragma unroll
                for (int j = 0; j < 4; j++)
                    mma_tf32(c[i][j], af[i][0], af[i][1], af[i][2], af[i][3],
                             bf[j][0], bf[j][1]);
        }
        __syncthreads();
    }

    // Epilogue: c0->(r0,cb), c1->(r0,cb+1), c2->(r1,cb), c3->(r1,cb+1)
#pragma unroll
    for (int i = 0; i < 4; i++) {
        int r0 = m0 + wm * 64 + i * 16 + gid;
        int r1 = r0 + 8;
#pragma unroll
        for (int j = 0; j < 4; j++) {
            int cb = n0 + wn * 32 + j * 8 + 2 * tig;
#pragma unroll
            for (int e = 0; e < 2; e++) {
                int cc = cb + e;
                float v0 = c[i][j][e]     + bias[cc];
                float v1 = c[i][j][e + 2] + bias[cc];
                if (headInterleave) {
                    int h = cc >> 6, d = cc & 63;
                    {
                        int b = r0 >> 10, n = r0 & 1023;
                        g_dummy_noop: ;
                        out[(size_t)(b * HEADS + h) * (SEQ * DK) + (size_t)n * DK + d] = v0;
                    }
                    {
                        int b = r1 >> 10, n = r1 & 1023;
                        out[(size_t)(b * HEADS + h) * (SEQ * DK) + (size_t)n * DK + d] = v1;
                    }
                } else {
                    out[(size_t)r0 * DMODEL + cc] = v0;
                    out[(size_t)r1 * DMODEL + cc] = v1;
                }
            }
        }
    }
}

// ---------------------------------------------------------------------------
// Fused flash attention (fp32 SIMT). 64q x 64k tiles, online softmax.
// Per-thread S-columns remapped to (tx + 16*j): consecutive lanes hit
// consecutive smem rows -> bank conflicts drop from ~8-way to ~2-way.
// ---------------------------------------------------------------------------
#define ASTRIDE 68
#define ATTN_SMEM_BYTES (4 * 64 * ASTRIDE * 4)

__global__ __launch_bounds__(256, 2)
void attn_kernel(const float* __restrict__ Bij,
                 const unsigned int* __restrict__ maskW)
{
    extern __shared__ float smem[];
    float* sQ  = smem;                  // [64][68]  [q][d]
    float* sK  = sQ  + 64 * ASTRIDE;    // [64][68]  [k][d]
    float* sVt = sK  + 64 * ASTRIDE;    // [64][68]  [d][k]
    float* sP  = sVt + 64 * ASTRIDE;    // [64][68]  bias, then probs [q][k]
    __shared__ unsigned char sM[64];

    const int b  = blockIdx.z;
    const int h  = blockIdx.y;
    const int q0 = blockIdx.x * 64;
    const int tid = threadIdx.x;
    const int ty = tid >> 4;    // rows 4*ty..4*ty+3
    const int tx = tid & 15;    // cols tx, tx+16, tx+32, tx+48
    const int bh = b * HEADS + h;
    const float scale = 0.125f;

    {
        const float* Qg = g_Q + (size_t)(bh * SEQ + q0) * DK;
        int r = tid >> 2, seg = tid & 3;
#pragma unroll
        for (int u = 0; u < 4; u++) {
            int cc = seg * 16 + u * 4;
            *(float4*)&sQ[r * ASTRIDE + cc] = *(const float4*)(Qg + r * DK + cc);
        }
    }

    float mI[4], lI[4], acc[4][4];
#pragma unroll
    for (int i = 0; i < 4; i++) {
        mI[i] = -INFINITY; lI[i] = 0.0f;
#pragma unroll
        for (int j = 0; j < 4; j++) acc[i][j] = 0.0f;
    }

    for (int kt = 0; kt < SEQ / 64; kt++) {
        const int k0 = kt * 64;
        __syncthreads();

        {
            int r = tid >> 2, seg = tid & 3;
            const float* Kg = g_K + (size_t)(bh * SEQ + k0) * DK;
            const float* Vg = g_V + (size_t)(bh * SEQ + k0) * DK;
            const float* Bg = Bij + ((size_t)bh * SEQ + (q0 + r)) * SEQ + k0;
#pragma unroll
            for (int u = 0; u < 4; u++) {
                int cc = seg * 16 + u * 4;
                *(float4*)&sK[r * ASTRIDE + cc] = *(const float4*)(Kg + r * DK + cc);
                float4 v = *(const float4*)(Vg + r * DK + cc);
                sVt[(cc + 0) * ASTRIDE + r] = v.x;
                sVt[(cc + 1) * ASTRIDE + r] = v.y;
                sVt[(cc + 2) * ASTRIDE + r] = v.z;
                sVt[(cc + 3) * ASTRIDE + r] = v.w;
                *(float4*)&sP[r * ASTRIDE + cc] = *(const float4*)(Bg + cc);
            }
            if (tid < 64) sM[tid] = (maskW[b * SEQ + k0 + tid] != 0u) ? 1 : 0;
        }
        __syncthreads();

        // S = Q K^T ; thread (ty,tx) -> rows 4ty+i, cols tx+16j
        float s[4][4];
#pragma unroll
        for (int i = 0; i < 4; i++)
#pragma unroll
            for (int j = 0; j < 4; j++) s[i][j] = 0.0f;

#pragma unroll
        for (int d = 0; d < 64; d += 4) {
            float4 qv[4], kv[4];
#pragma unroll
            for (int i = 0; i < 4; i++) qv[i] = *(float4*)&sQ[(4 * ty + i) * ASTRIDE + d];
#pragma unroll
            for (int j = 0; j < 4; j++) kv[j] = *(float4*)&sK[(tx + 16 * j) * ASTRIDE + d];
#pragma unroll
            for (int i = 0; i < 4; i++)
#pragma unroll
                for (int j = 0; j < 4; j++) {
                    s[i][j] = fmaf(qv[i].x, kv[j].x, s[i][j]);
                    s[i][j] = fmaf(qv[i].y, kv[j].y, s[i][j]);
                    s[i][j] = fmaf(qv[i].z, kv[j].z, s[i][j]);
                    s[i][j] = fmaf(qv[i].w, kv[j].w, s[i][j]);
                }
        }

        // bias + mask + online softmax
#pragma unroll
        for (int i = 0; i < 4; i++) {
            int rI = 4 * ty + i;
            float sv[4];
#pragma unroll
            for (int j = 0; j < 4; j++) {
                int cc = tx + 16 * j;
                float val = s[i][j] * scale + sP[rI * ASTRIDE + cc];
                sv[j] = sM[cc] ? val : -10000.0f;
            }
            float mx = fmaxf(fmaxf(sv[0], sv[1]), fmaxf(sv[2], sv[3]));
#pragma unroll
            for (int off = 8; off > 0; off >>= 1)
                mx = fmaxf(mx, __shfl_xor_sync(0xffffffffu, mx, off, 16));
            float mNew = fmaxf(mI[i], mx);
            float alpha = __expf(mI[i] - mNew);
            float rs = 0.0f;
#pragma unroll
            for (int j = 0; j < 4; j++) {
                float p = __expf(sv[j] - mNew);
                sP[rI * ASTRIDE + tx + 16 * j] = p;
                rs += p;
            }
#pragma unroll
            for (int off = 8; off > 0; off >>= 1)
                rs += __shfl_xor_sync(0xffffffffu, rs, off, 16);
            lI[i] = lI[i] * alpha + rs;
            mI[i] = mNew;
#pragma unroll
            for (int j = 0; j < 4; j++) acc[i][j] *= alpha;
        }
        __syncthreads();

        // O += P V ; acc cols = tx+16j (output dims)
#pragma unroll
        for (int kk = 0; kk < 64; kk += 4) {
            float4 pv[4], vv[4];
#pragma unroll
            for (int i = 0; i < 4; i++) pv[i] = *(float4*)&sP[(4 * ty + i) * ASTRIDE + kk];
#pragma unroll
            for (int j = 0; j < 4; j++) vv[j] = *(float4*)&sVt[(tx + 16 * j) * ASTRIDE + kk];
#pragma unroll
            for (int i = 0; i < 4; i++)
#pragma unroll
                for (int j = 0; j < 4; j++) {
                    acc[i][j] = fmaf(pv[i].x, vv[j].x, acc[i][j]);
                    acc[i][j] = fmaf(pv[i].y, vv[j].y, acc[i][j]);
                    acc[i][j] = fmaf(pv[i].z, vv[j].z, acc[i][j]);
                    acc[i][j] = fmaf(pv[i].w, vv[j].w, acc[i][j]);
                }
        }
    }

    // Epilogue: write [b, n, h*64 + d], d = tx+16j
    float* Og = g_O + ((size_t)b * SEQ + q0) * DMODEL + h * DK;
#pragma unroll
    for (int i = 0; i < 4; i++) {
        float inv = 1.0f / lI[i];
#pragma unroll
        for (int j = 0; j < 4; j++)
            Og[(size_t)(4 * ty + i) * DMODEL + tx + 16 * j] = acc[i][j] * inv;
    }
}

// ---------------------------------------------------------------------------
extern "C" void kernel_launch(void* const* d_in, const int* in_sizes, int n_in,
                              void* d_out, int out_size)
{
    // Identify inputs by element count (robust to metadata ordering)
    const float* X = 0; const float* Bij = 0; const void* maskP = 0;
    const float* Ws[4] = {0, 0, 0, 0};
    const float* bs[4] = {0, 0, 0, 0};
    int nW = 0, nB = 0;
    for (int i = 0; i < n_in; i++) {
        int sz = in_sizes[i];
        if (sz == BATCH * HEADS * SEQ * SEQ)      Bij  = (const float*)d_in[i];
        else if (sz == BATCH * SEQ * DMODEL)      X    = (const float*)d_in[i];
        else if (sz == BATCH * SEQ)               maskP = d_in[i];
        else if (sz == DMODEL * DMODEL && nW < 4) Ws[nW++] = (const float*)d_in[i];
        else if (sz == DMODEL && nB < 4)          bs[nB++] = (const float*)d_in[i];
    }
    const float *Wq = Ws[0], *Wk = Ws[1], *Wv = Ws[2], *Wo = Ws[3];
    const float *bq = bs[0], *bk = bs[1], *bv = bs[2], *bo = bs[3];
    float* out = (float*)d_out;

    float *qp, *kp, *vp, *op;
    cudaGetSymbolAddress((void**)&qp, g_Q);
    cudaGetSymbolAddress((void**)&kp, g_K);
    cudaGetSymbolAddress((void**)&vp, g_V);
    cudaGetSymbolAddress((void**)&op, g_O);

    cudaFuncSetAttribute(attn_kernel, cudaFuncAttributeMaxDynamicSharedMemorySize,
                         ATTN_SMEM_BYTES);

    dim3 gGemm(DMODEL / TBN, (BATCH * SEQ) / TBM);   // (8, 32)

    tf32_gemm_kernel<<<gGemm, 256>>>(X, Wq, bq, qp, 1);
    tf32_gemm_kernel<<<gGemm, 256>>>(X, Wk, bk, kp, 1);
    tf32_gemm_kernel<<<gGemm, 256>>>(X, Wv, bv, vp, 1);

    dim3 gAttn(SEQ / 64, HEADS, BATCH);              // (16, 16, 4)
    attn_kernel<<<gAttn, 256, ATTN_SMEM_BYTES>>>(Bij, (const unsigned int*)maskP);

    tf32_gemm_kernel<<<gGemm, 256>>>(op, Wo, bo, out, 0);
}

// round 5
// speedup vs baseline: 2.9182x; 1.3209x over previous
#include <cuda_runtime.h>
#include <cuda_bf16.h>
#include <math.h>

// Problem constants
#define BATCH 4
#define SEQ   1024
#define DMODEL 1024
#define HEADS 16
#define DK    64

// Scratch (device globals: allocation-free rule)
__device__ float g_Q[BATCH * HEADS * SEQ * DK];   // [b,h,n,d]
__device__ float g_K[BATCH * HEADS * SEQ * DK];
__device__ float g_V[BATCH * HEADS * SEQ * DK];
__device__ float g_O[BATCH * SEQ * DMODEL];       // [b,n,D] attention output

// ---------------------------------------------------------------------------
// tf32 helpers
// ---------------------------------------------------------------------------
__device__ __forceinline__ unsigned int f2tf32(float x) {
    unsigned int u;
    asm("cvt.rna.tf32.f32 %0, %1;" : "=r"(u) : "f"(x));
    return u;
}

__device__ __forceinline__ void mma_tf32(float c[4],
                                         unsigned int a0, unsigned int a1,
                                         unsigned int a2, unsigned int a3,
                                         unsigned int b0, unsigned int b1) {
    asm volatile(
        "mma.sync.aligned.m16n8k8.row.col.f32.tf32.tf32.f32 "
        "{%0,%1,%2,%3}, {%4,%5,%6,%7}, {%8,%9}, {%0,%1,%2,%3};\n"
        : "+f"(c[0]), "+f"(c[1]), "+f"(c[2]), "+f"(c[3])
        : "r"(a0), "r"(a1), "r"(a2), "r"(a3), "r"(b0), "r"(b1));
}

// ---------------------------------------------------------------------------
// tf32 tensor-core GEMM: out[4096,1024] = A[4096,1024] @ W[1024,1024] + bias
// (unchanged from R4 apart from dead-label cleanup)
// ---------------------------------------------------------------------------
#define TBM 128
#define TBN 128
#define TBK 16
#define AST 20
#define BST 136

__global__ __launch_bounds__(256, 2)
void tf32_gemm_kernel(const float* __restrict__ A,
                      const float* __restrict__ W,
                      const float* __restrict__ bias,
                      float* __restrict__ out,
                      int headInterleave)
{
    __shared__ float As[TBM][AST];
    __shared__ float Bs[TBK][BST];

    const int m0 = blockIdx.y * TBM;
    const int n0 = blockIdx.x * TBN;
    const int tid = threadIdx.x;
    const int wid = tid >> 5;
    const int lane = tid & 31;
    const int wm = wid >> 2;          // 0..1
    const int wn = wid & 3;           // 0..3
    const int gid = lane >> 2;        // 0..7
    const int tig = lane & 3;         // 0..3

    float c[4][4][4];
#pragma unroll
    for (int i = 0; i < 4; i++)
#pragma unroll
        for (int j = 0; j < 4; j++)
#pragma unroll
            for (int r = 0; r < 4; r++) c[i][j][r] = 0.0f;

    for (int k0 = 0; k0 < DMODEL; k0 += TBK) {
#pragma unroll
        for (int q = 0; q < 2; q++) {
            int idx = tid * 2 + q;
            int row = idx >> 2;
            int ks  = (idx & 3) * 4;
            float4 v = *(const float4*)(A + (size_t)(m0 + row) * DMODEL + k0 + ks);
            As[row][ks + 0] = __uint_as_float(f2tf32(v.x));
            As[row][ks + 1] = __uint_as_float(f2tf32(v.y));
            As[row][ks + 2] = __uint_as_float(f2tf32(v.z));
            As[row][ks + 3] = __uint_as_float(f2tf32(v.w));
        }
#pragma unroll
        for (int q = 0; q < 2; q++) {
            int idx = tid * 2 + q;
            int kk = idx >> 5;
            int cs = (idx & 31) * 4;
            float4 v = *(const float4*)(W + (size_t)(k0 + kk) * DMODEL + n0 + cs);
            Bs[kk][cs + 0] = __uint_as_float(f2tf32(v.x));
            Bs[kk][cs + 1] = __uint_as_float(f2tf32(v.y));
            Bs[kk][cs + 2] = __uint_as_float(f2tf32(v.z));
            Bs[kk][cs + 3] = __uint_as_float(f2tf32(v.w));
        }
        __syncthreads();

#pragma unroll
        for (int ks = 0; ks < 2; ks++) {
            const int kb = ks * 8;
            unsigned int af[4][4], bf[4][2];
#pragma unroll
            for (int i = 0; i < 4; i++) {
                int mb = wm * 64 + i * 16;
                af[i][0] = __float_as_uint(As[mb + gid    ][kb + tig]);
                af[i][1] = __float_as_uint(As[mb + gid + 8][kb + tig]);
                af[i][2] = __float_as_uint(As[mb + gid    ][kb + tig + 4]);
                af[i][3] = __float_as_uint(As[mb + gid + 8][kb + tig + 4]);
            }
#pragma unroll
            for (int j = 0; j < 4; j++) {
                int nb = wn * 32 + j * 8;
                bf[j][0] = __float_as_uint(Bs[kb + tig    ][nb + gid]);
                bf[j][1] = __float_as_uint(Bs[kb + tig + 4][nb + gid]);
            }
#pragma unroll
            for (int i = 0; i < 4; i++)
#pragma unroll
                for (int j = 0; j < 4; j++)
                    mma_tf32(c[i][j], af[i][0], af[i][1], af[i][2], af[i][3],
                             bf[j][0], bf[j][1]);
        }
        __syncthreads();
    }

#pragma unroll
    for (int i = 0; i < 4; i++) {
        int r0 = m0 + wm * 64 + i * 16 + gid;
        int r1 = r0 + 8;
#pragma unroll
        for (int j = 0; j < 4; j++) {
            int cb = n0 + wn * 32 + j * 8 + 2 * tig;
#pragma unroll
            for (int e = 0; e < 2; e++) {
                int cc = cb + e;
                float v0 = c[i][j][e]     + bias[cc];
                float v1 = c[i][j][e + 2] + bias[cc];
                if (headInterleave) {
                    int h = cc >> 6, d = cc & 63;
                    int b0i = r0 >> 10, n0i = r0 & 1023;
                    int b1i = r1 >> 10, n1i = r1 & 1023;
                    out[(size_t)(b0i * HEADS + h) * (SEQ * DK) + (size_t)n0i * DK + d] = v0;
                    out[(size_t)(b1i * HEADS + h) * (SEQ * DK) + (size_t)n1i * DK + d] = v1;
                } else {
                    out[(size_t)r0 * DMODEL + cc] = v0;
                    out[(size_t)r1 * DMODEL + cc] = v1;
                }
            }
        }
    }
}

// ---------------------------------------------------------------------------
// Tensor-core flash attention. 64q x 64k tiles, dk=64.
// 8 warps in 4(m) x 2(n) grid; warp tile 16x32 for both S=QK^T and O=PV.
// S/PV via mma.m16n8k8.tf32; softmax in fp32 with quad-shuffle + smem
// cross-warp (2-way) combines. P written to smem pre-rounded to tf32.
// V stored untransposed (PV B-frag reads sV[k][d] directly).
// ---------------------------------------------------------------------------
#define AT 68
#define ATTN_SMEM_BYTES ((4 * 64 * AT + 256) * 4)

__global__ __launch_bounds__(256, 2)
void attn_tc_kernel(const float* __restrict__ Bij,
                    const unsigned int* __restrict__ maskW)
{
    extern __shared__ float sm[];
    float* sQ   = sm;                 // [64][AT] tf32
    float* sK   = sQ + 64 * AT;       // [64][AT] tf32
    float* sV   = sK + 64 * AT;       // [64][AT] tf32
    float* sP   = sV + 64 * AT;       // [64][AT] bias fp32, then P tf32
    float* sMax = sP + 64 * AT;       // [64][2]
    float* sSum = sMax + 128;         // [64][2]
    __shared__ unsigned char sM[64];

    const int b  = blockIdx.z;
    const int h  = blockIdx.y;
    const int q0 = blockIdx.x * 64;
    const int tid  = threadIdx.x;
    const int wid  = tid >> 5;
    const int lane = tid & 31;
    const int wm = wid >> 1;          // 0..3  (m block of 16)
    const int wn = wid & 1;           // 0..1  (n block of 32)
    const int gid = lane >> 2;        // 0..7
    const int tig = lane & 3;         // 0..3
    const int bh = b * HEADS + h;
    const float scale = 0.125f;

    const int r0 = wm * 16 + gid;     // this thread's rows in the 64-q tile
    const int r1 = r0 + 8;

    // Load Q once (tf32)
    {
        const float* Qg = g_Q + (size_t)(bh * SEQ + q0) * DK;
        int r = tid >> 2, seg = tid & 3;
#pragma unroll
        for (int u = 0; u < 4; u++) {
            int cc = seg * 16 + u * 4;
            float4 v = *(const float4*)(Qg + r * DK + cc);
            sQ[r * AT + cc + 0] = __uint_as_float(f2tf32(v.x));
            sQ[r * AT + cc + 1] = __uint_as_float(f2tf32(v.y));
            sQ[r * AT + cc + 2] = __uint_as_float(f2tf32(v.z));
            sQ[r * AT + cc + 3] = __uint_as_float(f2tf32(v.w));
        }
    }

    float mI0 = -INFINITY, mI1 = -INFINITY, lI0 = 0.0f, lI1 = 0.0f;
    float o[4][4];
#pragma unroll
    for (int j = 0; j < 4; j++)
#pragma unroll
        for (int r = 0; r < 4; r++) o[j][r] = 0.0f;

    for (int kt = 0; kt < SEQ / 64; kt++) {
        const int k0 = kt * 64;
        __syncthreads();   // prior PV finished reading sP/sV

        // Load K, V (tf32) and bias tile (fp32, into sP)
        {
            int r = tid >> 2, seg = tid & 3;
            const float* Kg = g_K + (size_t)(bh * SEQ + k0) * DK;
            const float* Vg = g_V + (size_t)(bh * SEQ + k0) * DK;
            const float* Bg = Bij + ((size_t)bh * SEQ + (q0 + r)) * SEQ + k0;
#pragma unroll
            for (int u = 0; u < 4; u++) {
                int cc = seg * 16 + u * 4;
                float4 kv = *(const float4*)(Kg + r * DK + cc);
                sK[r * AT + cc + 0] = __uint_as_float(f2tf32(kv.x));
                sK[r * AT + cc + 1] = __uint_as_float(f2tf32(kv.y));
                sK[r * AT + cc + 2] = __uint_as_float(f2tf32(kv.z));
                sK[r * AT + cc + 3] = __uint_as_float(f2tf32(kv.w));
                float4 vv = *(const float4*)(Vg + r * DK + cc);
                sV[r * AT + cc + 0] = __uint_as_float(f2tf32(vv.x));
                sV[r * AT + cc + 1] = __uint_as_float(f2tf32(vv.y));
                sV[r * AT + cc + 2] = __uint_as_float(f2tf32(vv.z));
                sV[r * AT + cc + 3] = __uint_as_float(f2tf32(vv.w));
                *(float4*)&sP[r * AT + cc] = *(const float4*)(Bg + cc);
            }
            if (tid < 64) sM[tid] = (maskW[b * SEQ + k0 + tid] != 0u) ? 1 : 0;
        }
        __syncthreads();

        // S = Q K^T : warp tile 16x32, accumulate over d
        float c[4][4];
#pragma unroll
        for (int j = 0; j < 4; j++)
#pragma unroll
            for (int r = 0; r < 4; r++) c[j][r] = 0.0f;

#pragma unroll
        for (int kb = 0; kb < 64; kb += 8) {
            unsigned int a0 = __float_as_uint(sQ[r0 * AT + kb + tig]);
            unsigned int a1 = __float_as_uint(sQ[r1 * AT + kb + tig]);
            unsigned int a2 = __float_as_uint(sQ[r0 * AT + kb + tig + 4]);
            unsigned int a3 = __float_as_uint(sQ[r1 * AT + kb + tig + 4]);
#pragma unroll
            for (int j = 0; j < 4; j++) {
                int nb = wn * 32 + j * 8;
                unsigned int b0 = __float_as_uint(sK[(nb + gid) * AT + kb + tig]);
                unsigned int b1 = __float_as_uint(sK[(nb + gid) * AT + kb + tig + 4]);
                mma_tf32(c[j], a0, a1, a2, a3, b0, b1);
            }
        }

        // scale + bias + mask; per-row partial max
        float vals[4][4];
        float pm0 = -INFINITY, pm1 = -INFINITY;
#pragma unroll
        for (int j = 0; j < 4; j++) {
#pragma unroll
            for (int e = 0; e < 2; e++) {
                int cc = wn * 32 + j * 8 + 2 * tig + e;
                bool mk = sM[cc];
                float v0 = mk ? fmaf(c[j][e],     scale, sP[r0 * AT + cc]) : -10000.0f;
                float v1 = mk ? fmaf(c[j][e + 2], scale, sP[r1 * AT + cc]) : -10000.0f;
                vals[j][e]     = v0;
                vals[j][e + 2] = v1;
                pm0 = fmaxf(pm0, v0);
                pm1 = fmaxf(pm1, v1);
            }
        }
        pm0 = fmaxf(pm0, __shfl_xor_sync(0xffffffffu, pm0, 1));
        pm0 = fmaxf(pm0, __shfl_xor_sync(0xffffffffu, pm0, 2));
        pm1 = fmaxf(pm1, __shfl_xor_sync(0xffffffffu, pm1, 1));
        pm1 = fmaxf(pm1, __shfl_xor_sync(0xffffffffu, pm1, 2));
        if (tig == 0) { sMax[r0 * 2 + wn] = pm0; sMax[r1 * 2 + wn] = pm1; }
        __syncthreads();

        float mN0 = fmaxf(mI0, fmaxf(sMax[r0 * 2], sMax[r0 * 2 + 1]));
        float mN1 = fmaxf(mI1, fmaxf(sMax[r1 * 2], sMax[r1 * 2 + 1]));
        float al0 = __expf(mI0 - mN0);
        float al1 = __expf(mI1 - mN1);
        mI0 = mN0; mI1 = mN1;

        float ps0 = 0.0f, ps1 = 0.0f;
#pragma unroll
        for (int j = 0; j < 4; j++) {
#pragma unroll
            for (int e = 0; e < 2; e++) {
                int cc = wn * 32 + j * 8 + 2 * tig + e;
                float p0 = __expf(vals[j][e]     - mN0);
                float p1 = __expf(vals[j][e + 2] - mN1);
                ps0 += p0; ps1 += p1;
                sP[r0 * AT + cc] = __uint_as_float(f2tf32(p0));
                sP[r1 * AT + cc] = __uint_as_float(f2tf32(p1));
            }
        }
        ps0 += __shfl_xor_sync(0xffffffffu, ps0, 1);
        ps0 += __shfl_xor_sync(0xffffffffu, ps0, 2);
        ps1 += __shfl_xor_sync(0xffffffffu, ps1, 1);
        ps1 += __shfl_xor_sync(0xffffffffu, ps1, 2);
        if (tig == 0) { sSum[r0 * 2 + wn] = ps0; sSum[r1 * 2 + wn] = ps1; }

        // rescale O accumulators (register-only)
#pragma unroll
        for (int j = 0; j < 4; j++) {
            o[j][0] *= al0; o[j][1] *= al0;
            o[j][2] *= al1; o[j][3] *= al1;
        }
        __syncthreads();

        lI0 = lI0 * al0 + sSum[r0 * 2] + sSum[r0 * 2 + 1];
        lI1 = lI1 * al1 + sSum[r1 * 2] + sSum[r1 * 2 + 1];

        // O += P V
#pragma unroll
        for (int kb = 0; kb < 64; kb += 8) {
            unsigned int a0 = __float_as_uint(sP[r0 * AT + kb + tig]);
            unsigned int a1 = __float_as_uint(sP[r1 * AT + kb + tig]);
            unsigned int a2 = __float_as_uint(sP[r0 * AT + kb + tig + 4]);
            unsigned int a3 = __float_as_uint(sP[r1 * AT + kb + tig + 4]);
#pragma unroll
            for (int j = 0; j < 4; j++) {
                int nb = wn * 32 + j * 8;
                unsigned int b0 = __float_as_uint(sV[(kb + tig)     * AT + nb + gid]);
                unsigned int b1 = __float_as_uint(sV[(kb + tig + 4) * AT + nb + gid]);
                mma_tf32(o[j], a0, a1, a2, a3, b0, b1);
            }
        }
    }

    // Epilogue: write [b, q0+row, h*64 + d]
    float inv0 = 1.0f / lI0;
    float inv1 = 1.0f / lI1;
    float* Og = g_O + ((size_t)b * SEQ + q0) * DMODEL + h * DK;
#pragma unroll
    for (int j = 0; j < 4; j++) {
#pragma unroll
        for (int e = 0; e < 2; e++) {
            int cc = wn * 32 + j * 8 + 2 * tig + e;
            Og[(size_t)r0 * DMODEL + cc] = o[j][e]     * inv0;
            Og[(size_t)r1 * DMODEL + cc] = o[j][e + 2] * inv1;
        }
    }
}

// ---------------------------------------------------------------------------
extern "C" void kernel_launch(void* const* d_in, const int* in_sizes, int n_in,
                              void* d_out, int out_size)
{
    // Identify inputs by element count (robust to metadata ordering)
    const float* X = 0; const float* Bij = 0; const void* maskP = 0;
    const float* Ws[4] = {0, 0, 0, 0};
    const float* bs[4] = {0, 0, 0, 0};
    int nW = 0, nB = 0;
    for (int i = 0; i < n_in; i++) {
        int sz = in_sizes[i];
        if (sz == BATCH * HEADS * SEQ * SEQ)      Bij  = (const float*)d_in[i];
        else if (sz == BATCH * SEQ * DMODEL)      X    = (const float*)d_in[i];
        else if (sz == BATCH * SEQ)               maskP = d_in[i];
        else if (sz == DMODEL * DMODEL && nW < 4) Ws[nW++] = (const float*)d_in[i];
        else if (sz == DMODEL && nB < 4)          bs[nB++] = (const float*)d_in[i];
    }
    const float *Wq = Ws[0], *Wk = Ws[1], *Wv = Ws[2], *Wo = Ws[3];
    const float *bq = bs[0], *bk = bs[1], *bv = bs[2], *bo = bs[3];
    float* out = (float*)d_out;

    float *qp, *kp, *vp, *op;
    cudaGetSymbolAddress((void**)&qp, g_Q);
    cudaGetSymbolAddress((void**)&kp, g_K);
    cudaGetSymbolAddress((void**)&vp, g_V);
    cudaGetSymbolAddress((void**)&op, g_O);

    cudaFuncSetAttribute(attn_tc_kernel, cudaFuncAttributeMaxDynamicSharedMemorySize,
                         ATTN_SMEM_BYTES);

    dim3 gGemm(DMODEL / TBN, (BATCH * SEQ) / TBM);   // (8, 32)

    tf32_gemm_kernel<<<gGemm, 256>>>(X, Wq, bq, qp, 1);
    tf32_gemm_kernel<<<gGemm, 256>>>(X, Wk, bk, kp, 1);
    tf32_gemm_kernel<<<gGemm, 256>>>(X, Wv, bv, vp, 1);

    dim3 gAttn(SEQ / 64, HEADS, BATCH);              // (16, 16, 4)
    attn_tc_kernel<<<gAttn, 256, ATTN_SMEM_BYTES>>>(Bij, (const unsigned int*)maskP);

    tf32_gemm_kernel<<<gGemm, 256>>>(op, Wo, bo, out, 0);
}

// round 7
// speedup vs baseline: 2.9991x; 1.0277x over previous
#include <cuda_runtime.h>
#include <cuda_bf16.h>
#include <math.h>

// Problem constants
#define BATCH 4
#define SEQ   1024
#define DMODEL 1024
#define HEADS 16
#define DK    64

// Scratch (device globals: allocation-free rule)
__device__ float g_Q[BATCH * HEADS * SEQ * DK];   // [b,h,n,d]
__device__ float g_K[BATCH * HEADS * SEQ * DK];
__device__ float g_V[BATCH * HEADS * SEQ * DK];
__device__ float g_O[BATCH * SEQ * DMODEL];       // [b,n,D] attention output

// ---------------------------------------------------------------------------
// tf32 helpers
// ---------------------------------------------------------------------------
__device__ __forceinline__ unsigned int f2tf32(float x) {
    unsigned int u;
    asm("cvt.rna.tf32.f32 %0, %1;" : "=r"(u) : "f"(x));
    return u;
}
__device__ __forceinline__ float tf32f(float x) {
    return __uint_as_float(f2tf32(x));
}

__device__ __forceinline__ void mma_tf32(float c[4],
                                         unsigned int a0, unsigned int a1,
                                         unsigned int a2, unsigned int a3,
                                         unsigned int b0, unsigned int b1) {
    asm volatile(
        "mma.sync.aligned.m16n8k8.row.col.f32.tf32.tf32.f32 "
        "{%0,%1,%2,%3}, {%4,%5,%6,%7}, {%8,%9}, {%0,%1,%2,%3};\n"
        : "+f"(c[0]), "+f"(c[1]), "+f"(c[2]), "+f"(c[3])
        : "r"(a0), "r"(a1), "r"(a2), "r"(a3), "r"(b0), "r"(b1));
}

// ---------------------------------------------------------------------------
// tf32 tensor-core GEMM (unchanged from R5)
// ---------------------------------------------------------------------------
#define TBM 128
#define TBN 128
#define TBK 16
#define AST 20
#define BST 136

__global__ __launch_bounds__(256, 2)
void tf32_gemm_kernel(const float* __restrict__ A,
                      const float* __restrict__ W,
                      const float* __restrict__ bias,
                      float* __restrict__ out,
                      int headInterleave)
{
    __shared__ float As[TBM][AST];
    __shared__ float Bs[TBK][BST];

    const int m0 = blockIdx.y * TBM;
    const int n0 = blockIdx.x * TBN;
    const int tid = threadIdx.x;
    const int wid = tid >> 5;
    const int lane = tid & 31;
    const int wm = wid >> 2;
    const int wn = wid & 3;
    const int gid = lane >> 2;
    const int tig = lane & 3;

    float c[4][4][4];
#pragma unroll
    for (int i = 0; i < 4; i++)
#pragma unroll
        for (int j = 0; j < 4; j++)
#pragma unroll
            for (int r = 0; r < 4; r++) c[i][j][r] = 0.0f;

    for (int k0 = 0; k0 < DMODEL; k0 += TBK) {
#pragma unroll
        for (int q = 0; q < 2; q++) {
            int idx = tid * 2 + q;
            int row = idx >> 2;
            int ks  = (idx & 3) * 4;
            float4 v = *(const float4*)(A + (size_t)(m0 + row) * DMODEL + k0 + ks);
            As[row][ks + 0] = tf32f(v.x);
            As[row][ks + 1] = tf32f(v.y);
            As[row][ks + 2] = tf32f(v.z);
            As[row][ks + 3] = tf32f(v.w);
        }
#pragma unroll
        for (int q = 0; q < 2; q++) {
            int idx = tid * 2 + q;
            int kk = idx >> 5;
            int cs = (idx & 31) * 4;
            float4 v = *(const float4*)(W + (size_t)(k0 + kk) * DMODEL + n0 + cs);
            Bs[kk][cs + 0] = tf32f(v.x);
            Bs[kk][cs + 1] = tf32f(v.y);
            Bs[kk][cs + 2] = tf32f(v.z);
            Bs[kk][cs + 3] = tf32f(v.w);
        }
        __syncthreads();

#pragma unroll
        for (int ks = 0; ks < 2; ks++) {
            const int kb = ks * 8;
            unsigned int af[4][4], bf[4][2];
#pragma unroll
            for (int i = 0; i < 4; i++) {
                int mb = wm * 64 + i * 16;
                af[i][0] = __float_as_uint(As[mb + gid    ][kb + tig]);
                af[i][1] = __float_as_uint(As[mb + gid + 8][kb + tig]);
                af[i][2] = __float_as_uint(As[mb + gid    ][kb + tig + 4]);
                af[i][3] = __float_as_uint(As[mb + gid + 8][kb + tig + 4]);
            }
#pragma unroll
            for (int j = 0; j < 4; j++) {
                int nb = wn * 32 + j * 8;
                bf[j][0] = __float_as_uint(Bs[kb + tig    ][nb + gid]);
                bf[j][1] = __float_as_uint(Bs[kb + tig + 4][nb + gid]);
            }
#pragma unroll
            for (int i = 0; i < 4; i++)
#pragma unroll
                for (int j = 0; j < 4; j++)
                    mma_tf32(c[i][j], af[i][0], af[i][1], af[i][2], af[i][3],
                             bf[j][0], bf[j][1]);
        }
        __syncthreads();
    }

#pragma unroll
    for (int i = 0; i < 4; i++) {
        int r0 = m0 + wm * 64 + i * 16 + gid;
        int r1 = r0 + 8;
#pragma unroll
        for (int j = 0; j < 4; j++) {
            int cb = n0 + wn * 32 + j * 8 + 2 * tig;
#pragma unroll
            for (int e = 0; e < 2; e++) {
                int cc = cb + e;
                float v0 = c[i][j][e]     + bias[cc];
                float v1 = c[i][j][e + 2] + bias[cc];
                if (headInterleave) {
                    int h = cc >> 6, d = cc & 63;
                    int b0i = r0 >> 10, n0i = r0 & 1023;
                    int b1i = r1 >> 10, n1i = r1 & 1023;
                    out[(size_t)(b0i * HEADS + h) * (SEQ * DK) + (size_t)n0i * DK + d] = v0;
                    out[(size_t)(b1i * HEADS + h) * (SEQ * DK) + (size_t)n1i * DK + d] = v1;
                } else {
                    out[(size_t)r0 * DMODEL + cc] = v0;
                    out[(size_t)r1 * DMODEL + cc] = v1;
                }
            }
        }
    }
}

// ---------------------------------------------------------------------------
// Tensor-core flash attention v2.
// CTA tile 128q x 64k; 8 warps as 4(m) x 2(n); warp tile 32x32.
// AT=72 (72 mod 32 = 8) + pi-permuted columns within 8-groups:
//   pi(u) = 2*(u&3) + (u>>2)  -> fragment pair (tig, tig+4) adjacent.
// sQ/sK/sP fragment loads: conflict-free LDS.64.
// sV fragment loads: conflict-free scalar (banks 8*tig + pi(gid)).
// ---------------------------------------------------------------------------
#define AT 72
#define ATTN_SMEM_BYTES ((384 * AT + 512) * 4)   // 112640 B

__global__ __launch_bounds__(256, 2)
void attn_tc2_kernel(const float* __restrict__ Bij,
                     const unsigned int* __restrict__ maskW)
{
    extern __shared__ float sm[];
    float* sQ   = sm;                 // [128][AT] tf32, d pi-permuted
    float* sK   = sQ + 128 * AT;      // [64][AT]  tf32, d pi-permuted
    float* sV   = sK + 64 * AT;       // [64][AT]  tf32, d pi-permuted
    float* sP   = sV + 64 * AT;       // [128][AT] bias fp32 (plain), then P tf32 (k pi-permuted)
    float* sMax = sP + 128 * AT;      // [128][2]
    float* sSum = sMax + 256;         // [128][2]
    __shared__ unsigned char sM[64];

    const int b  = blockIdx.z;
    const int h  = blockIdx.y;
    const int q0 = blockIdx.x * 128;
    const int tid  = threadIdx.x;
    const int wid  = tid >> 5;
    const int lane = tid & 31;
    const int wm = wid >> 1;          // 0..3
    const int wn = wid & 1;           // 0..1
    const int gid = lane >> 2;        // 0..7
    const int tig = lane & 3;         // 0..3
    const int bh = b * HEADS + h;
    const float scale = 0.125f;

    const int pg  = 2 * (gid & 3) + (gid >> 2);                    // pi(gid)
    const int pu0 = 2 * ((2 * tig) & 3) + ((2 * tig) >> 2);        // pi(2t)
    const int pu1 = 2 * ((2 * tig + 1) & 3) + ((2 * tig + 1) >> 2);// pi(2t+1)

    int rr[4];  // thread's 4 q-rows: [mtile*2 + half]
    rr[0] = wm * 32 + gid;      rr[1] = rr[0] + 8;
    rr[2] = wm * 32 + 16 + gid; rr[3] = rr[2] + 8;

    // Stage Q once (tf32, pi-permuted): 128 rows x 64 d
    {
        const float* Qg = g_Q + (size_t)(bh * SEQ + q0) * DK;
        int r = tid >> 2, seg = tid & 3;
#pragma unroll
        for (int half = 0; half < 2; half++) {
            int row = r + half * 64;
#pragma unroll
            for (int u4 = 0; u4 < 4; u4++) {
                float4 v = *(const float4*)(Qg + (size_t)row * DK + seg * 16 + u4 * 4);
                int base = row * AT + seg * 16 + (u4 >> 1) * 8 + (u4 & 1);
                sQ[base + 0] = tf32f(v.x);
                sQ[base + 2] = tf32f(v.y);
                sQ[base + 4] = tf32f(v.z);
                sQ[base + 6] = tf32f(v.w);
            }
        }
    }

    float mI[4], lI[4];
#pragma unroll
    for (int r = 0; r < 4; r++) { mI[r] = -INFINITY; lI[r] = 0.0f; }
    float o[2][4][4];
#pragma unroll
    for (int i = 0; i < 2; i++)
#pragma unroll
        for (int j = 0; j < 4; j++)
#pragma unroll
            for (int r = 0; r < 4; r++) o[i][j][r] = 0.0f;

    for (int kt = 0; kt < SEQ / 64; kt++) {
        const int k0 = kt * 64;
        __syncthreads();   // prev PV done reading sK/sV/sP (covers Q staging on iter 0)

        // Stage K, V (tf32, pi), bias (fp32, plain), mask
        {
            int r = tid >> 2, seg = tid & 3;
            const float* Kg = g_K + (size_t)(bh * SEQ + k0) * DK;
            const float* Vg = g_V + (size_t)(bh * SEQ + k0) * DK;
#pragma unroll
            for (int u4 = 0; u4 < 4; u4++) {
                float4 kv = *(const float4*)(Kg + (size_t)r * DK + seg * 16 + u4 * 4);
                float4 vv = *(const float4*)(Vg + (size_t)r * DK + seg * 16 + u4 * 4);
                int base = r * AT + seg * 16 + (u4 >> 1) * 8 + (u4 & 1);
                sK[base + 0] = tf32f(kv.x);
                sK[base + 2] = tf32f(kv.y);
                sK[base + 4] = tf32f(kv.z);
                sK[base + 6] = tf32f(kv.w);
                sV[base + 0] = tf32f(vv.x);
                sV[base + 2] = tf32f(vv.y);
                sV[base + 4] = tf32f(vv.z);
                sV[base + 6] = tf32f(vv.w);
            }
            const float* Bg = Bij + ((size_t)bh * SEQ + (q0 + r)) * SEQ + k0;
#pragma unroll
            for (int u4 = 0; u4 < 4; u4++) {
                int cc = seg * 16 + u4 * 4;
                *(float4*)&sP[r * AT + cc]        = *(const float4*)(Bg + cc);
                *(float4*)&sP[(r + 64) * AT + cc] = *(const float4*)(Bg + (size_t)64 * SEQ + cc);
            }
            if (tid < 64) sM[tid] = (maskW[b * SEQ + k0 + tid] != 0u) ? 1 : 0;
        }
        __syncthreads();

        // ---- S = Q K^T : warp 32x32, c[2 mtiles][4 ntiles][4] ----
        float c[2][4][4];
#pragma unroll
        for (int i = 0; i < 2; i++)
#pragma unroll
            for (int j = 0; j < 4; j++)
#pragma unroll
                for (int r = 0; r < 4; r++) c[i][j][r] = 0.0f;

#pragma unroll
        for (int kb = 0; kb < 64; kb += 8) {
            float2 qa[2][2];
            qa[0][0] = *(float2*)&sQ[rr[0] * AT + kb + 2 * tig];
            qa[0][1] = *(float2*)&sQ[rr[1] * AT + kb + 2 * tig];
            qa[1][0] = *(float2*)&sQ[rr[2] * AT + kb + 2 * tig];
            qa[1][1] = *(float2*)&sQ[rr[3] * AT + kb + 2 * tig];
#pragma unroll
            for (int j = 0; j < 4; j++) {
                int key = wn * 32 + j * 8 + gid;
                float2 kf = *(float2*)&sK[key * AT + kb + 2 * tig];
                unsigned int b0 = __float_as_uint(kf.x);
                unsigned int b1 = __float_as_uint(kf.y);
#pragma unroll
                for (int i = 0; i < 2; i++)
                    mma_tf32(c[i][j],
                             __float_as_uint(qa[i][0].x), __float_as_uint(qa[i][1].x),
                             __float_as_uint(qa[i][0].y), __float_as_uint(qa[i][1].y),
                             b0, b1);
            }
        }

        // ---- scale + bias + mask; per-row partial max (reuse c as vals) ----
        float pm[4] = {-INFINITY, -INFINITY, -INFINITY, -INFINITY};
#pragma unroll
        for (int i = 0; i < 2; i++) {
#pragma unroll
            for (int j = 0; j < 4; j++) {
                int cc0 = wn * 32 + j * 8 + 2 * tig;
                int cc1 = cc0 + 1;
                bool mk0 = sM[cc0], mk1 = sM[cc1];
                float v0 = mk0 ? fmaf(c[i][j][0], scale, sP[rr[2*i]   * AT + cc0]) : -10000.0f;
                float v1 = mk1 ? fmaf(c[i][j][1], scale, sP[rr[2*i]   * AT + cc1]) : -10000.0f;
                float v2 = mk0 ? fmaf(c[i][j][2], scale, sP[rr[2*i+1] * AT + cc0]) : -10000.0f;
                float v3 = mk1 ? fmaf(c[i][j][3], scale, sP[rr[2*i+1] * AT + cc1]) : -10000.0f;
                c[i][j][0] = v0; c[i][j][1] = v1; c[i][j][2] = v2; c[i][j][3] = v3;
                pm[2*i]   = fmaxf(pm[2*i],   fmaxf(v0, v1));
                pm[2*i+1] = fmaxf(pm[2*i+1], fmaxf(v2, v3));
            }
        }
#pragma unroll
        for (int r = 0; r < 4; r++) {
            pm[r] = fmaxf(pm[r], __shfl_xor_sync(0xffffffffu, pm[r], 1));
            pm[r] = fmaxf(pm[r], __shfl_xor_sync(0xffffffffu, pm[r], 2));
        }
        if (tig == 0) {
#pragma unroll
            for (int r = 0; r < 4; r++) sMax[rr[r] * 2 + wn] = pm[r];
        }
        __syncthreads();

        float mN[4], al[4], ps[4];
#pragma unroll
        for (int r = 0; r < 4; r++) {
            mN[r] = fmaxf(mI[r], fmaxf(sMax[rr[r] * 2], sMax[rr[r] * 2 + 1]));
            al[r] = __expf(mI[r] - mN[r]);
            mI[r] = mN[r];
            ps[r] = 0.0f;
        }

        // exp + write P (tf32, pi-permuted k cols)
#pragma unroll
        for (int i = 0; i < 2; i++) {
#pragma unroll
            for (int j = 0; j < 4; j++) {
                int base0 = rr[2*i]     * AT + wn * 32 + j * 8;
                int base1 = rr[2*i + 1] * AT + wn * 32 + j * 8;
                float p0 = __expf(c[i][j][0] - mN[2*i]);
                float p1 = __expf(c[i][j][1] - mN[2*i]);
                float p2 = __expf(c[i][j][2] - mN[2*i+1]);
                float p3 = __expf(c[i][j][3] - mN[2*i+1]);
                sP[base0 + pu0] = tf32f(p0);
                sP[base0 + pu1] = tf32f(p1);
                sP[base1 + pu0] = tf32f(p2);
                sP[base1 + pu1] = tf32f(p3);
                ps[2*i]   += p0 + p1;
                ps[2*i+1] += p2 + p3;
            }
        }
#pragma unroll
        for (int r = 0; r < 4; r++) {
            ps[r] += __shfl_xor_sync(0xffffffffu, ps[r], 1);
            ps[r] += __shfl_xor_sync(0xffffffffu, ps[r], 2);
        }
        if (tig == 0) {
#pragma unroll
            for (int r = 0; r < 4; r++) sSum[rr[r] * 2 + wn] = ps[r];
        }

        // rescale O accumulators
#pragma unroll
        for (int i = 0; i < 2; i++)
#pragma unroll
            for (int j = 0; j < 4; j++) {
                o[i][j][0] *= al[2*i];   o[i][j][1] *= al[2*i];
                o[i][j][2] *= al[2*i+1]; o[i][j][3] *= al[2*i+1];
            }
        __syncthreads();

#pragma unroll
        for (int r = 0; r < 4; r++)
            lI[r] = lI[r] * al[r] + sSum[rr[r] * 2] + sSum[rr[r] * 2 + 1];

        // ---- O += P V ----
#pragma unroll
        for (int kb = 0; kb < 64; kb += 8) {
            float2 pa[2][2];
            pa[0][0] = *(float2*)&sP[rr[0] * AT + kb + 2 * tig];
            pa[0][1] = *(float2*)&sP[rr[1] * AT + kb + 2 * tig];
            pa[1][0] = *(float2*)&sP[rr[2] * AT + kb + 2 * tig];
            pa[1][1] = *(float2*)&sP[rr[3] * AT + kb + 2 * tig];
#pragma unroll
            for (int j = 0; j < 4; j++) {
                int dcol = wn * 32 + j * 8 + pg;
                unsigned int b0 = __float_as_uint(sV[(kb + tig)     * AT + dcol]);
                unsigned int b1 = __float_as_uint(sV[(kb + tig + 4) * AT + dcol]);
#pragma unroll
                for (int i = 0; i < 2; i++)
                    mma_tf32(o[i][j],
                             __float_as_uint(pa[i][0].x), __float_as_uint(pa[i][1].x),
                             __float_as_uint(pa[i][0].y), __float_as_uint(pa[i][1].y),
                             b0, b1);
            }
        }
    }

    // Epilogue: write [b, q0+row, h*64 + d]
    float inv[4];
#pragma unroll
    for (int r = 0; r < 4; r++) inv[r] = 1.0f / lI[r];
    float* Og = g_O + ((size_t)b * SEQ + q0) * DMODEL + h * DK;
#pragma unroll
    for (int i = 0; i < 2; i++) {
#pragma unroll
        for (int j = 0; j < 4; j++) {
#pragma unroll
            for (int e = 0; e < 2; e++) {
                int cc = wn * 32 + j * 8 + 2 * tig + e;
                Og[(size_t)rr[2*i]     * DMODEL + cc] = o[i][j][e]     * inv[2*i];
                Og[(size_t)rr[2*i + 1] * DMODEL + cc] = o[i][j][e + 2] * inv[2*i+1];
            }
        }
    }
}

// ---------------------------------------------------------------------------
extern "C" void kernel_launch(void* const* d_in, const int* in_sizes, int n_in,
                              void* d_out, int out_size)
{
    // Identify inputs by element count (robust to metadata ordering)
    const float* X = 0; const float* Bij = 0; const void* maskP = 0;
    const float* Ws[4] = {0, 0, 0, 0};
    const float* bs[4] = {0, 0, 0, 0};
    int nW = 0, nB = 0;
    for (int i = 0; i < n_in; i++) {
        int sz = in_sizes[i];
        if (sz == BATCH * HEADS * SEQ * SEQ)      Bij  = (const float*)d_in[i];
        else if (sz == BATCH * SEQ * DMODEL)      X    = (const float*)d_in[i];
        else if (sz == BATCH * SEQ)               maskP = d_in[i];
        else if (sz == DMODEL * DMODEL && nW < 4) Ws[nW++] = (const float*)d_in[i];
        else if (sz == DMODEL && nB < 4)          bs[nB++] = (const float*)d_in[i];
    }
    const float *Wq = Ws[0], *Wk = Ws[1], *Wv = Ws[2], *Wo = Ws[3];
    const float *bq = bs[0], *bk = bs[1], *bv = bs[2], *bo = bs[3];
    float* out = (float*)d_out;

    float *qp, *kp, *vp, *op;
    cudaGetSymbolAddress((void**)&qp, g_Q);
    cudaGetSymbolAddress((void**)&kp, g_K);
    cudaGetSymbolAddress((void**)&vp, g_V);
    cudaGetSymbolAddress((void**)&op, g_O);

    cudaFuncSetAttribute(attn_tc2_kernel, cudaFuncAttributeMaxDynamicSharedMemorySize,
                         ATTN_SMEM_BYTES);

    dim3 gGemm(DMODEL / TBN, (BATCH * SEQ) / TBM);   // (8, 32)

    tf32_gemm_kernel<<<gGemm, 256>>>(X, Wq, bq, qp, 1);
    tf32_gemm_kernel<<<gGemm, 256>>>(X, Wk, bk, kp, 1);
    tf32_gemm_kernel<<<gGemm, 256>>>(X, Wv, bv, vp, 1);

    dim3 gAttn(SEQ / 128, HEADS, BATCH);             // (8, 16, 4)
    attn_tc2_kernel<<<gAttn, 256, ATTN_SMEM_BYTES>>>(Bij, (const unsigned int*)maskP);

    tf32_gemm_kernel<<<gGemm, 256>>>(op, Wo, bo, out, 0);
}

// round 12
// speedup vs baseline: 4.2459x; 1.4157x over previous
#include <cuda_runtime.h>
#include <cuda_bf16.h>
#include <math.h>

// Problem constants
#define BATCH 4
#define SEQ   1024
#define DMODEL 1024
#define HEADS 16
#define DK    64

// Scratch (device globals: allocation-free rule)
__device__ float g_Q[BATCH * HEADS * SEQ * DK];   // [b,h,n,d]  tf32-rounded, d pi-permuted
__device__ float g_K[BATCH * HEADS * SEQ * DK];
__device__ float g_V[BATCH * HEADS * SEQ * DK];
__device__ float g_O[BATCH * SEQ * DMODEL];       // [b,n,D] attention output (tf32-rounded)
__device__ float g_Xr[BATCH * SEQ * DMODEL];      // X rounded to tf32
__device__ float g_Wr[4 * DMODEL * DMODEL];       // Wq,Wk,Wv,Wo rounded to tf32

// ---------------------------------------------------------------------------
// tf32 + cp.async helpers
// ---------------------------------------------------------------------------
__device__ __forceinline__ unsigned int f2tf32(float x) {
    unsigned int u;
    asm("cvt.rna.tf32.f32 %0, %1;" : "=r"(u) : "f"(x));
    return u;
}
__device__ __forceinline__ float tf32f(float x) {
    return __uint_as_float(f2tf32(x));
}

__device__ __forceinline__ void mma_tf32(float c[4],
                                         unsigned int a0, unsigned int a1,
                                         unsigned int a2, unsigned int a3,
                                         unsigned int b0, unsigned int b1) {
    asm volatile(
        "mma.sync.aligned.m16n8k8.row.col.f32.tf32.tf32.f32 "
        "{%0,%1,%2,%3}, {%4,%5,%6,%7}, {%8,%9}, {%0,%1,%2,%3};\n"
        : "+f"(c[0]), "+f"(c[1]), "+f"(c[2]), "+f"(c[3])
        : "r"(a0), "r"(a1), "r"(a2), "r"(a3), "r"(b0), "r"(b1));
}

__device__ __forceinline__ void cp16(void* smem_dst, const void* gsrc) {
    unsigned int s = (unsigned int)__cvta_generic_to_shared(smem_dst);
    asm volatile("cp.async.cg.shared.global [%0], [%1], 16;\n" :: "r"(s), "l"(gsrc));
}
#define CP_COMMIT() asm volatile("cp.async.commit_group;\n" ::)
#define CP_WAIT1()  asm volatile("cp.async.wait_group 1;\n" ::)

// ---------------------------------------------------------------------------
// Rounding kernels: X and W* -> tf32 once (staging becomes raw byte copy)
// ---------------------------------------------------------------------------
__global__ void round_x_kernel(const float* __restrict__ X) {
    int i = blockIdx.x * blockDim.x + threadIdx.x;   // float4 index, grid exact
    float4 v = ((const float4*)X)[i];
    v.x = tf32f(v.x); v.y = tf32f(v.y); v.z = tf32f(v.z); v.w = tf32f(v.w);
    ((float4*)g_Xr)[i] = v;
}

__global__ void round_w_kernel(const float* __restrict__ w0, const float* __restrict__ w1,
                               const float* __restrict__ w2, const float* __restrict__ w3) {
    int i = blockIdx.x * blockDim.x + threadIdx.x;   // 0..2^20-1 float4
    int sel = i >> 18;                               // 262144 float4 per W
    int off = i & 262143;
    const float* src = (sel == 0) ? w0 : (sel == 1) ? w1 : (sel == 2) ? w2 : w3;
    float4 v = ((const float4*)src)[off];
    v.x = tf32f(v.x); v.y = tf32f(v.y); v.z = tf32f(v.z); v.w = tf32f(v.w);
    ((float4*)g_Wr)[i] = v;
}

// ---------------------------------------------------------------------------
// tf32 GEMM with 2-stage cp.async pipeline.
// out[4096,1024] = A[4096,1024] @ W[1024,1024] + bias. A/W pre-rounded tf32.
// headInterleave=1: write [b,h,n,d] with d pi-permuted + tf32-rounded.
// ---------------------------------------------------------------------------
#define TBM 128
#define TBN 128
#define TBK 16
#define AST 20
#define BST 136

__global__ __launch_bounds__(256, 2)
void tf32_gemm2_kernel(const float* __restrict__ A,
                       const float* __restrict__ W,
                       const float* __restrict__ bias,
                       float* __restrict__ out,
                       int headInterleave)
{
    __shared__ __align__(16) float As[2][TBM][AST];
    __shared__ __align__(16) float Bs[2][TBK][BST];

    const int m0 = blockIdx.y * TBM;
    const int n0 = blockIdx.x * TBN;
    const int tid = threadIdx.x;
    const int wid = tid >> 5;
    const int lane = tid & 31;
    const int wm = wid >> 2;
    const int wn = wid & 3;
    const int gid = lane >> 2;
    const int tig = lane & 3;

    float c[4][4][4];
#pragma unroll
    for (int i = 0; i < 4; i++)
#pragma unroll
        for (int j = 0; j < 4; j++)
#pragma unroll
            for (int r = 0; r < 4; r++) c[i][j][r] = 0.0f;

    // ---- stage tile macro ----
#define GEMM_STAGE(buf, tidx) do {                                             \
        int k0s = (tidx) * TBK;                                                \
        _Pragma("unroll")                                                      \
        for (int q = 0; q < 2; q++) {                                          \
            int cch = q * 256 + tid;                                           \
            int row = cch >> 2, sg = (cch & 3) << 2;                           \
            cp16(&As[buf][row][sg],                                            \
                 A + (size_t)(m0 + row) * DMODEL + k0s + sg);                  \
        }                                                                      \
        _Pragma("unroll")                                                      \
        for (int q = 0; q < 2; q++) {                                          \
            int cch = q * 256 + tid;                                           \
            int kk = cch >> 5, cs = (cch & 31) << 2;                           \
            cp16(&Bs[buf][kk][cs],                                             \
                 W + (size_t)(k0s + kk) * DMODEL + n0 + cs);                   \
        }                                                                      \
    } while (0)

    GEMM_STAGE(0, 0);
    CP_COMMIT();

    for (int t = 0; t < DMODEL / TBK; t++) {
        int buf = t & 1;
        if (t < DMODEL / TBK - 1) GEMM_STAGE(buf ^ 1, t + 1);
        CP_COMMIT();
        CP_WAIT1();
        __syncthreads();

#pragma unroll
        for (int ks = 0; ks < 2; ks++) {
            const int kb = ks * 8;
            unsigned int af[4][4], bf[4][2];
#pragma unroll
            for (int i = 0; i < 4; i++) {
                int mb = wm * 64 + i * 16;
                af[i][0] = __float_as_uint(As[buf][mb + gid    ][kb + tig]);
                af[i][1] = __float_as_uint(As[buf][mb + gid + 8][kb + tig]);
                af[i][2] = __float_as_uint(As[buf][mb + gid    ][kb + tig + 4]);
                af[i][3] = __float_as_uint(As[buf][mb + gid + 8][kb + tig + 4]);
            }
#pragma unroll
            for (int j = 0; j < 4; j++) {
                int nb = wn * 32 + j * 8;
                bf[j][0] = __float_as_uint(Bs[buf][kb + tig    ][nb + gid]);
                bf[j][1] = __float_as_uint(Bs[buf][kb + tig + 4][nb + gid]);
            }
#pragma unroll
            for (int i = 0; i < 4; i++)
#pragma unroll
                for (int j = 0; j < 4; j++)
                    mma_tf32(c[i][j], af[i][0], af[i][1], af[i][2], af[i][3],
                             bf[j][0], bf[j][1]);
        }
        __syncthreads();
    }
#undef GEMM_STAGE

#pragma unroll
    for (int i = 0; i < 4; i++) {
        int r0 = m0 + wm * 64 + i * 16 + gid;
        int r1 = r0 + 8;
#pragma unroll
        for (int j = 0; j < 4; j++) {
            int cb = n0 + wn * 32 + j * 8 + 2 * tig;
#pragma unroll
            for (int e = 0; e < 2; e++) {
                int cc = cb + e;
                float v0 = c[i][j][e]     + bias[cc];
                float v1 = c[i][j][e + 2] + bias[cc];
                if (headInterleave) {
                    int h = cc >> 6, d = cc & 63;
                    int d2 = (d & 56) | (2 * (d & 3) + ((d & 7) >> 2));  // pi within 8-group
                    int b0i = r0 >> 10, n0i = r0 & 1023;
                    int b1i = r1 >> 10, n1i = r1 & 1023;
                    out[(size_t)(b0i * HEADS + h) * (SEQ * DK) + (size_t)n0i * DK + d2] = tf32f(v0);
                    out[(size_t)(b1i * HEADS + h) * (SEQ * DK) + (size_t)n1i * DK + d2] = tf32f(v1);
                } else {
                    out[(size_t)r0 * DMODEL + cc] = v0;
                    out[(size_t)r1 * DMODEL + cc] = v1;
                }
            }
        }
    }
}

// ---------------------------------------------------------------------------
// Tensor-core flash attention v3: 2-stage cp.async pipeline.
// CTA tile 128q x 64k; 8 warps 4(m)x2(n); warp tile 32x32; AT=72, pi layout.
// K/V/bias double-buffered; g_Q/g_K/g_V arrive pre-rounded + pi-permuted.
// ---------------------------------------------------------------------------
#define AT 72
#define SQ_OFF   0
#define SK_OFF   (128 * AT)                   // 9216
#define SV_OFF   (SK_OFF + 2 * 64 * AT)       // 18432
#define SP_OFF   (SV_OFF + 2 * 64 * AT)       // 27648
#define SMAX_OFF (SP_OFF + 2 * 128 * AT)      // 46080
#define SSUM_OFF (SMAX_OFF + 256)
#define SMSK_OFF (SSUM_OFF + 256)
#define ATTN_SMEM_BYTES ((SMSK_OFF + 1024) * 4)   // 190464 B

__global__ __launch_bounds__(256, 1)
void attn_tc3_kernel(const float* __restrict__ Bij,
                     const unsigned int* __restrict__ maskW)
{
    extern __shared__ float sm[];
    float* sMax = sm + SMAX_OFF;
    float* sSum = sm + SSUM_OFF;
    unsigned int* sMsk = (unsigned int*)(sm + SMSK_OFF);

    const int b  = blockIdx.z;
    const int h  = blockIdx.y;
    const int q0 = blockIdx.x * 128;
    const int tid  = threadIdx.x;
    const int lane = tid & 31;
    const int wid  = tid >> 5;
    const int wm = wid >> 1;
    const int wn = wid & 1;
    const int gid = lane >> 2;
    const int tig = lane & 3;
    const int bh = b * HEADS + h;
    const float scale = 0.125f;

    const int pg  = 2 * (gid & 3) + (gid >> 2);
    const int pu0 = 2 * ((2 * tig) & 3) + ((2 * tig) >> 2);
    const int pu1 = 2 * ((2 * tig + 1) & 3) + ((2 * tig + 1) >> 2);

    int rr[4];
    rr[0] = wm * 32 + gid;      rr[1] = rr[0] + 8;
    rr[2] = wm * 32 + 16 + gid; rr[3] = rr[2] + 8;

    const float* Qg = g_Q + (size_t)(bh * SEQ + q0) * DK;
    const float* Kg = g_K + (size_t)bh * SEQ * DK;
    const float* Vg = g_V + (size_t)bh * SEQ * DK;
    const float* Bg = Bij + ((size_t)bh * SEQ + q0) * SEQ;

    // ---- stage macro: K/V (64x64) + bias (128x64) for tile kt into buf ----
#define ATTN_STAGE(buf, kt) do {                                               \
        float* sKb = sm + SK_OFF + (buf) * 64 * AT;                            \
        float* sVb = sm + SV_OFF + (buf) * 64 * AT;                            \
        float* sPb = sm + SP_OFF + (buf) * 128 * AT;                           \
        const float* Kt = Kg + (size_t)(kt) * 64 * DK;                         \
        const float* Vt = Vg + (size_t)(kt) * 64 * DK;                         \
        const float* Bt = Bg + (kt) * 64;                                      \
        _Pragma("unroll")                                                      \
        for (int t = 0; t < 4; t++) {                                          \
            int cch = t * 256 + tid;                                           \
            int row = cch >> 4, col = (cch & 15) << 2;                         \
            cp16(&sKb[row * AT + col], Kt + row * DK + col);                   \
            cp16(&sVb[row * AT + col], Vt + row * DK + col);                   \
        }                                                                      \
        _Pragma("unroll")                                                      \
        for (int t = 0; t < 8; t++) {                                          \
            int cch = t * 256 + tid;                                           \
            int row = cch >> 4, col = (cch & 15) << 2;                         \
            cp16(&sPb[row * AT + col], Bt + (size_t)row * SEQ + col);          \
        }                                                                      \
    } while (0)

    // Prologue: Q (128x64), mask row (1024 words), stage tile 0
    {
#pragma unroll
        for (int t = 0; t < 8; t++) {
            int cch = t * 256 + tid;
            int row = cch >> 4, col = (cch & 15) << 2;
            cp16(&sm[SQ_OFF + row * AT + col], Qg + (size_t)row * DK + col);
        }
        cp16(&sMsk[tid * 4], maskW + (size_t)b * SEQ + tid * 4);
        ATTN_STAGE(0, 0);
        CP_COMMIT();
    }

    float mI[4], lI[4];
#pragma unroll
    for (int r = 0; r < 4; r++) { mI[r] = -INFINITY; lI[r] = 0.0f; }
    float o[2][4][4];
#pragma unroll
    for (int i = 0; i < 2; i++)
#pragma unroll
        for (int j = 0; j < 4; j++)
#pragma unroll
            for (int r = 0; r < 4; r++) o[i][j][r] = 0.0f;

    for (int kt = 0; kt < SEQ / 64; kt++) {
        const int buf = kt & 1;
        const int k0c = kt * 64;
        float* sKb = sm + SK_OFF + buf * 64 * AT;
        float* sVb = sm + SV_OFF + buf * 64 * AT;
        float* sPb = sm + SP_OFF + buf * 128 * AT;

        if (kt + 1 < SEQ / 64) ATTN_STAGE(buf ^ 1, kt + 1);
        CP_COMMIT();
        CP_WAIT1();
        __syncthreads();

        // ---- S = Q K^T ----
        float c[2][4][4];
#pragma unroll
        for (int i = 0; i < 2; i++)
#pragma unroll
            for (int j = 0; j < 4; j++)
#pragma unroll
                for (int r = 0; r < 4; r++) c[i][j][r] = 0.0f;

#pragma unroll
        for (int kb = 0; kb < 64; kb += 8) {
            float2 qa[2][2];
            qa[0][0] = *(float2*)&sm[SQ_OFF + rr[0] * AT + kb + 2 * tig];
            qa[0][1] = *(float2*)&sm[SQ_OFF + rr[1] * AT + kb + 2 * tig];
            qa[1][0] = *(float2*)&sm[SQ_OFF + rr[2] * AT + kb + 2 * tig];
            qa[1][1] = *(float2*)&sm[SQ_OFF + rr[3] * AT + kb + 2 * tig];
#pragma unroll
            for (int j = 0; j < 4; j++) {
                int key = wn * 32 + j * 8 + gid;
                float2 kf = *(float2*)&sKb[key * AT + kb + 2 * tig];
                unsigned int b0 = __float_as_uint(kf.x);
                unsigned int b1 = __float_as_uint(kf.y);
#pragma unroll
                for (int i = 0; i < 2; i++)
                    mma_tf32(c[i][j],
                             __float_as_uint(qa[i][0].x), __float_as_uint(qa[i][1].x),
                             __float_as_uint(qa[i][0].y), __float_as_uint(qa[i][1].y),
                             b0, b1);
            }
        }

        // ---- scale + bias + mask; row max ----
        float pm[4] = {-INFINITY, -INFINITY, -INFINITY, -INFINITY};
#pragma unroll
        for (int i = 0; i < 2; i++) {
#pragma unroll
            for (int j = 0; j < 4; j++) {
                int cc0 = wn * 32 + j * 8 + 2 * tig;
                int cc1 = cc0 + 1;
                bool mk0 = sMsk[k0c + cc0] != 0u;
                bool mk1 = sMsk[k0c + cc1] != 0u;
                float v0 = mk0 ? fmaf(c[i][j][0], scale, sPb[rr[2*i]   * AT + cc0]) : -10000.0f;
                float v1 = mk1 ? fmaf(c[i][j][1], scale, sPb[rr[2*i]   * AT + cc1]) : -10000.0f;
                float v2 = mk0 ? fmaf(c[i][j][2], scale, sPb[rr[2*i+1] * AT + cc0]) : -10000.0f;
                float v3 = mk1 ? fmaf(c[i][j][3], scale, sPb[rr[2*i+1] * AT + cc1]) : -10000.0f;
                c[i][j][0] = v0; c[i][j][1] = v1; c[i][j][2] = v2; c[i][j][3] = v3;
                pm[2*i]   = fmaxf(pm[2*i],   fmaxf(v0, v1));
                pm[2*i+1] = fmaxf(pm[2*i+1], fmaxf(v2, v3));
            }
        }
#pragma unroll
        for (int r = 0; r < 4; r++) {
            pm[r] = fmaxf(pm[r], __shfl_xor_sync(0xffffffffu, pm[r], 1));
            pm[r] = fmaxf(pm[r], __shfl_xor_sync(0xffffffffu, pm[r], 2));
        }
        if (tig == 0) {
#pragma unroll
            for (int r = 0; r < 4; r++) sMax[rr[r] * 2 + wn] = pm[r];
        }
        __syncthreads();

        float mN[4], al[4], ps[4];
#pragma unroll
        for (int r = 0; r < 4; r++) {
            mN[r] = fmaxf(mI[r], fmaxf(sMax[rr[r] * 2], sMax[rr[r] * 2 + 1]));
            al[r] = __expf(mI[r] - mN[r]);
            mI[r] = mN[r];
            ps[r] = 0.0f;
        }

        // exp + write P (tf32, pi cols)
#pragma unroll
        for (int i = 0; i < 2; i++) {
#pragma unroll
            for (int j = 0; j < 4; j++) {
                int base0 = rr[2*i]     * AT + wn * 32 + j * 8;
                int base1 = rr[2*i + 1] * AT + wn * 32 + j * 8;
                float p0 = __expf(c[i][j][0] - mN[2*i]);
                float p1 = __expf(c[i][j][1] - mN[2*i]);
                float p2 = __expf(c[i][j][2] - mN[2*i+1]);
                float p3 = __expf(c[i][j][3] - mN[2*i+1]);
                sPb[base0 + pu0] = tf32f(p0);
                sPb[base0 + pu1] = tf32f(p1);
                sPb[base1 + pu0] = tf32f(p2);
                sPb[base1 + pu1] = tf32f(p3);
                ps[2*i]   += p0 + p1;
                ps[2*i+1] += p2 + p3;
            }
        }
#pragma unroll
        for (int r = 0; r < 4; r++) {
            ps[r] += __shfl_xor_sync(0xffffffffu, ps[r], 1);
            ps[r] += __shfl_xor_sync(0xffffffffu, ps[r], 2);
        }
        if (tig == 0) {
#pragma unroll
            for (int r = 0; r < 4; r++) sSum[rr[r] * 2 + wn] = ps[r];
        }

#pragma unroll
        for (int i = 0; i < 2; i++)
#pragma unroll
            for (int j = 0; j < 4; j++) {
                o[i][j][0] *= al[2*i];   o[i][j][1] *= al[2*i];
                o[i][j][2] *= al[2*i+1]; o[i][j][3] *= al[2*i+1];
            }
        __syncthreads();

#pragma unroll
        for (int r = 0; r < 4; r++)
            lI[r] = lI[r] * al[r] + sSum[rr[r] * 2] + sSum[rr[r] * 2 + 1];

        // ---- O += P V ----
#pragma unroll
        for (int kb = 0; kb < 64; kb += 8) {
            float2 pa[2][2];
            pa[0][0] = *(float2*)&sPb[rr[0] * AT + kb + 2 * tig];
            pa[0][1] = *(float2*)&sPb[rr[1] * AT + kb + 2 * tig];
            pa[1][0] = *(float2*)&sPb[rr[2] * AT + kb + 2 * tig];
            pa[1][1] = *(float2*)&sPb[rr[3] * AT + kb + 2 * tig];
#pragma unroll
            for (int j = 0; j < 4; j++) {
                int dcol = wn * 32 + j * 8 + pg;
                unsigned int b0 = __float_as_uint(sVb[(kb + tig)     * AT + dcol]);
                unsigned int b1 = __float_as_uint(sVb[(kb + tig + 4) * AT + dcol]);
#pragma unroll
                for (int i = 0; i < 2; i++)
                    mma_tf32(o[i][j],
                             __float_as_uint(pa[i][0].x), __float_as_uint(pa[i][1].x),
                             __float_as_uint(pa[i][0].y), __float_as_uint(pa[i][1].y),
                             b0, b1);
            }
        }
        __syncthreads();   // release buf before next iter's prefetch overwrites it
    }
#undef ATTN_STAGE

    // Epilogue: write [b, q0+row, h*64 + d], tf32-rounded for final GEMM
    float inv[4];
#pragma unroll
    for (int r = 0; r < 4; r++) inv[r] = 1.0f / lI[r];
    float* Og = g_O + ((size_t)b * SEQ + q0) * DMODEL + h * DK;
#pragma unroll
    for (int i = 0; i < 2; i++) {
#pragma unroll
        for (int j = 0; j < 4; j++) {
#pragma unroll
            for (int e = 0; e < 2; e++) {
                int cc = wn * 32 + j * 8 + 2 * tig + e;
                Og[(size_t)rr[2*i]     * DMODEL + cc] = tf32f(o[i][j][e]     * inv[2*i]);
                Og[(size_t)rr[2*i + 1] * DMODEL + cc] = tf32f(o[i][j][e + 2] * inv[2*i+1]);
            }
        }
    }
}

// ---------------------------------------------------------------------------
extern "C" void kernel_launch(void* const* d_in, const int* in_sizes, int n_in,
                              void* d_out, int out_size)
{
    // Identify inputs by element count (robust to metadata ordering)
    const float* X = 0; const float* Bij = 0; const void* maskP = 0;
    const float* Ws[4] = {0, 0, 0, 0};
    const float* bs[4] = {0, 0, 0, 0};
    int nW = 0, nB = 0;
    for (int i = 0; i < n_in; i++) {
        int sz = in_sizes[i];
        if (sz == BATCH * HEADS * SEQ * SEQ)      Bij  = (const float*)d_in[i];
        else if (sz == BATCH * SEQ * DMODEL)      X    = (const float*)d_in[i];
        else if (sz == BATCH * SEQ)               maskP = d_in[i];
        else if (sz == DMODEL * DMODEL && nW < 4) Ws[nW++] = (const float*)d_in[i];
        else if (sz == DMODEL && nB < 4)          bs[nB++] = (const float*)d_in[i];
    }
    const float *Wq = Ws[0], *Wk = Ws[1], *Wv = Ws[2], *Wo = Ws[3];
    const float *bq = bs[0], *bk = bs[1], *bv = bs[2], *bo = bs[3];
    float* out = (float*)d_out;

    float *qp, *kp, *vp, *op, *xr, *wr;
    cudaGetSymbolAddress((void**)&qp, g_Q);
    cudaGetSymbolAddress((void**)&kp, g_K);
    cudaGetSymbolAddress((void**)&vp, g_V);
    cudaGetSymbolAddress((void**)&op, g_O);
    cudaGetSymbolAddress((void**)&xr, g_Xr);
    cudaGetSymbolAddress((void**)&wr, g_Wr);

    cudaFuncSetAttribute(attn_tc3_kernel, cudaFuncAttributeMaxDynamicSharedMemorySize,
                         ATTN_SMEM_BYTES);

    // Pre-round X and weights to tf32
    round_x_kernel<<<4096, 256>>>(X);                 // 4M floats = 1M float4
    round_w_kernel<<<4096, 256>>>(Wq, Wk, Wv, Wo);    // 4x1M floats = 1M float4

    dim3 gGemm(DMODEL / TBN, (BATCH * SEQ) / TBM);    // (8, 32)
    const int WSZ = DMODEL * DMODEL;

    tf32_gemm2_kernel<<<gGemm, 256>>>(xr, wr + 0 * WSZ, bq, qp, 1);
    tf32_gemm2_kernel<<<gGemm, 256>>>(xr, wr + 1 * WSZ, bk, kp, 1);
    tf32_gemm2_kernel<<<gGemm, 256>>>(xr, wr + 2 * WSZ, bv, vp, 1);

    dim3 gAttn(SEQ / 128, HEADS, BATCH);              // (8, 16, 4)
    attn_tc3_kernel<<<gAttn, 256, ATTN_SMEM_BYTES>>>(Bij, (const unsigned int*)maskP);

    tf32_gemm2_kernel<<<gGemm, 256>>>(op, wr + 3 * WSZ, bo, out, 0);
}

// round 15
// speedup vs baseline: 4.3714x; 1.0295x over previous
#include <cuda_runtime.h>
#include <cuda_bf16.h>
#include <math.h>

// Problem constants
#define BATCH 4
#define SEQ   1024
#define DMODEL 1024
#define HEADS 16
#define DK    64

// Scratch (device globals: allocation-free rule)
__device__ float g_Q[BATCH * HEADS * SEQ * DK];   // [b,h,n,d]  tf32-rounded, d pi-permuted
__device__ float g_K[BATCH * HEADS * SEQ * DK];
__device__ float g_V[BATCH * HEADS * SEQ * DK];
__device__ float g_O[BATCH * SEQ * DMODEL];       // [b,n,D] attention output (tf32-rounded)
__device__ float g_Xr[BATCH * SEQ * DMODEL];      // X rounded to tf32
__device__ float g_Wr[4 * DMODEL * DMODEL];       // Wq,Wk,Wv,Wo rounded to tf32

// ---------------------------------------------------------------------------
// tf32 + cp.async helpers
// ---------------------------------------------------------------------------
__device__ __forceinline__ unsigned int f2tf32(float x) {
    unsigned int u;
    asm("cvt.rna.tf32.f32 %0, %1;" : "=r"(u) : "f"(x));
    return u;
}
__device__ __forceinline__ float tf32f(float x) {
    return __uint_as_float(f2tf32(x));
}

__device__ __forceinline__ void mma_tf32(float c[4],
                                         unsigned int a0, unsigned int a1,
                                         unsigned int a2, unsigned int a3,
                                         unsigned int b0, unsigned int b1) {
    asm volatile(
        "mma.sync.aligned.m16n8k8.row.col.f32.tf32.tf32.f32 "
        "{%0,%1,%2,%3}, {%4,%5,%6,%7}, {%8,%9}, {%0,%1,%2,%3};\n"
        : "+f"(c[0]), "+f"(c[1]), "+f"(c[2]), "+f"(c[3])
        : "r"(a0), "r"(a1), "r"(a2), "r"(a3), "r"(b0), "r"(b1));
}

__device__ __forceinline__ void cp16(void* smem_dst, const void* gsrc) {
    unsigned int s = (unsigned int)__cvta_generic_to_shared(smem_dst);
    asm volatile("cp.async.cg.shared.global [%0], [%1], 16;\n" :: "r"(s), "l"(gsrc));
}
#define CP_COMMIT() asm volatile("cp.async.commit_group;\n" ::)
#define CP_WAIT1()  asm volatile("cp.async.wait_group 1;\n" ::)

// ---------------------------------------------------------------------------
// Rounding kernels: X and W* -> tf32 once (staging becomes raw byte copy)
// ---------------------------------------------------------------------------
__global__ void round_x_kernel(const float* __restrict__ X) {
    int i = blockIdx.x * blockDim.x + threadIdx.x;
    float4 v = ((const float4*)X)[i];
    v.x = tf32f(v.x); v.y = tf32f(v.y); v.z = tf32f(v.z); v.w = tf32f(v.w);
    ((float4*)g_Xr)[i] = v;
}

__global__ void round_w_kernel(const float* __restrict__ w0, const float* __restrict__ w1,
                               const float* __restrict__ w2, const float* __restrict__ w3) {
    int i = blockIdx.x * blockDim.x + threadIdx.x;
    int sel = i >> 18;
    int off = i & 262143;
    const float* src = (sel == 0) ? w0 : (sel == 1) ? w1 : (sel == 2) ? w2 : w3;
    float4 v = ((const float4*)src)[off];
    v.x = tf32f(v.x); v.y = tf32f(v.y); v.z = tf32f(v.z); v.w = tf32f(v.w);
    ((float4*)g_Wr)[i] = v;
}

// ---------------------------------------------------------------------------
// tf32 GEMM v3: TBK=32 (4 k-steps per barrier), 2-stage cp.async pipeline,
// optional QKV fusion over blockIdx.z (z selects W, bias, and destination).
// Tile buffers in DYNAMIC smem (71.7 KB > 48 KB static limit).
// qkvMode=1: dst = g_Q/g_K/g_V by z, [b,h,n,d] pi-permuted + tf32-rounded.
// qkvMode=0: out row-major (single z).
// ---------------------------------------------------------------------------
#define TBM 128
#define TBN 128
#define TBK 32
#define AST 36     // 36 mod 32 = 4  -> A frag banks 4*gid+tig, conflict-free
#define BST 136    // 136 mod 32 = 8 -> B frag banks 8*tig+gid, conflict-free
#define GAS (TBM * AST)              // 4608 floats per A buffer
#define GBS (TBK * BST)              // 4352 floats per B buffer
#define GEMM_SMEM_BYTES ((2 * GAS + 2 * GBS) * 4)   // 71680 B

__global__ __launch_bounds__(256, 2)
void tf32_gemm3_kernel(const float* __restrict__ A,
                       const float* __restrict__ Wbase,
                       const float* __restrict__ bias0,
                       const float* __restrict__ bias1,
                       const float* __restrict__ bias2,
                       float* __restrict__ out,
                       int qkvMode)
{
    extern __shared__ __align__(16) float gsm[];
    // layout: As[2][TBM][AST], Bs[2][TBK][BST]
    float* AsB = gsm;
    float* BsB = gsm + 2 * GAS;

    const int z  = blockIdx.z;
    const float* W    = Wbase + (size_t)z * DMODEL * DMODEL;
    const float* bias = (z == 0) ? bias0 : (z == 1) ? bias1 : bias2;

    const int m0 = blockIdx.y * TBM;
    const int n0 = blockIdx.x * TBN;
    const int tid = threadIdx.x;
    const int wid = tid >> 5;
    const int lane = tid & 31;
    const int wm = wid >> 2;
    const int wn = wid & 3;
    const int gid = lane >> 2;
    const int tig = lane & 3;

    float c[4][4][4];
#pragma unroll
    for (int i = 0; i < 4; i++)
#pragma unroll
        for (int j = 0; j < 4; j++)
#pragma unroll
            for (int r = 0; r < 4; r++) c[i][j][r] = 0.0f;

#define GEMM_STAGE(buf, tidx) do {                                             \
        int k0s = (tidx) * TBK;                                                \
        float* Asb = AsB + (buf) * GAS;                                        \
        float* Bsb = BsB + (buf) * GBS;                                        \
        _Pragma("unroll")                                                      \
        for (int q = 0; q < 4; q++) {                                          \
            int cch = q * 256 + tid;                                           \
            int row = cch >> 3, sg = (cch & 7) << 2;                           \
            cp16(&Asb[row * AST + sg],                                         \
                 A + (size_t)(m0 + row) * DMODEL + k0s + sg);                  \
        }                                                                      \
        _Pragma("unroll")                                                      \
        for (int q = 0; q < 4; q++) {                                          \
            int cch = q * 256 + tid;                                           \
            int kk = cch >> 5, cs = (cch & 31) << 2;                           \
            cp16(&Bsb[kk * BST + cs],                                          \
                 W + (size_t)(k0s + kk) * DMODEL + n0 + cs);                   \
        }                                                                      \
    } while (0)

    GEMM_STAGE(0, 0);
    CP_COMMIT();

    for (int t = 0; t < DMODEL / TBK; t++) {
        int buf = t & 1;
        if (t < DMODEL / TBK - 1) GEMM_STAGE(buf ^ 1, t + 1);
        CP_COMMIT();
        CP_WAIT1();
        __syncthreads();

        const float* Asb = AsB + buf * GAS;
        const float* Bsb = BsB + buf * GBS;

#pragma unroll
        for (int ks = 0; ks < 4; ks++) {
            const int kb = ks * 8;
            unsigned int af[4][4], bf[4][2];
#pragma unroll
            for (int i = 0; i < 4; i++) {
                int mb = wm * 64 + i * 16;
                af[i][0] = __float_as_uint(Asb[(mb + gid    ) * AST + kb + tig]);
                af[i][1] = __float_as_uint(Asb[(mb + gid + 8) * AST + kb + tig]);
                af[i][2] = __float_as_uint(Asb[(mb + gid    ) * AST + kb + tig + 4]);
                af[i][3] = __float_as_uint(Asb[(mb + gid + 8) * AST + kb + tig + 4]);
            }
#pragma unroll
            for (int j = 0; j < 4; j++) {
                int nb = wn * 32 + j * 8;
                bf[j][0] = __float_as_uint(Bsb[(kb + tig    ) * BST + nb + gid]);
                bf[j][1] = __float_as_uint(Bsb[(kb + tig + 4) * BST + nb + gid]);
            }
#pragma unroll
            for (int i = 0; i < 4; i++)
#pragma unroll
                for (int j = 0; j < 4; j++)
                    mma_tf32(c[i][j], af[i][0], af[i][1], af[i][2], af[i][3],
                             bf[j][0], bf[j][1]);
        }
        __syncthreads();
    }
#undef GEMM_STAGE

    // Destination select for QKV fusion
    float* dst = out;
    if (qkvMode) dst = (z == 0) ? g_Q : (z == 1) ? g_K : g_V;

#pragma unroll
    for (int i = 0; i < 4; i++) {
        int r0 = m0 + wm * 64 + i * 16 + gid;
        int r1 = r0 + 8;
#pragma unroll
        for (int j = 0; j < 4; j++) {
            int cb = n0 + wn * 32 + j * 8 + 2 * tig;
#pragma unroll
            for (int e = 0; e < 2; e++) {
                int cc = cb + e;
                float v0 = c[i][j][e]     + bias[cc];
                float v1 = c[i][j][e + 2] + bias[cc];
                if (qkvMode) {
                    int h = cc >> 6, d = cc & 63;
                    int d2 = (d & 56) | (2 * (d & 3) + ((d & 7) >> 2));  // pi within 8-group
                    int b0i = r0 >> 10, n0i = r0 & 1023;
                    int b1i = r1 >> 10, n1i = r1 & 1023;
                    dst[(size_t)(b0i * HEADS + h) * (SEQ * DK) + (size_t)n0i * DK + d2] = tf32f(v0);
                    dst[(size_t)(b1i * HEADS + h) * (SEQ * DK) + (size_t)n1i * DK + d2] = tf32f(v1);
                } else {
                    dst[(size_t)r0 * DMODEL + cc] = v0;
                    dst[(size_t)r1 * DMODEL + cc] = v1;
                }
            }
        }
    }
}

// ---------------------------------------------------------------------------
// Tensor-core flash attention v3 (unchanged from R12, which passed).
// ---------------------------------------------------------------------------
#define AT 72
#define SQ_OFF   0
#define SK_OFF   (128 * AT)
#define SV_OFF   (SK_OFF + 2 * 64 * AT)
#define SP_OFF   (SV_OFF + 2 * 64 * AT)
#define SMAX_OFF (SP_OFF + 2 * 128 * AT)
#define SSUM_OFF (SMAX_OFF + 256)
#define SMSK_OFF (SSUM_OFF + 256)
#define ATTN_SMEM_BYTES ((SMSK_OFF + 1024) * 4)   // 190464 B

__global__ __launch_bounds__(256, 1)
void attn_tc3_kernel(const float* __restrict__ Bij,
                     const unsigned int* __restrict__ maskW)
{
    extern __shared__ float sm[];
    float* sMax = sm + SMAX_OFF;
    float* sSum = sm + SSUM_OFF;
    unsigned int* sMsk = (unsigned int*)(sm + SMSK_OFF);

    const int b  = blockIdx.z;
    const int h  = blockIdx.y;
    const int q0 = blockIdx.x * 128;
    const int tid  = threadIdx.x;
    const int lane = tid & 31;
    const int wid  = tid >> 5;
    const int wm = wid >> 1;
    const int wn = wid & 1;
    const int gid = lane >> 2;
    const int tig = lane & 3;
    const int bh = b * HEADS + h;
    const float scale = 0.125f;

    const int pg  = 2 * (gid & 3) + (gid >> 2);
    const int pu0 = 2 * ((2 * tig) & 3) + ((2 * tig) >> 2);
    const int pu1 = 2 * ((2 * tig + 1) & 3) + ((2 * tig + 1) >> 2);

    int rr[4];
    rr[0] = wm * 32 + gid;      rr[1] = rr[0] + 8;
    rr[2] = wm * 32 + 16 + gid; rr[3] = rr[2] + 8;

    const float* Qg = g_Q + (size_t)(bh * SEQ + q0) * DK;
    const float* Kg = g_K + (size_t)bh * SEQ * DK;
    const float* Vg = g_V + (size_t)bh * SEQ * DK;
    const float* Bg = Bij + ((size_t)bh * SEQ + q0) * SEQ;

#define ATTN_STAGE(buf, kt) do {                                               \
        float* sKb = sm + SK_OFF + (buf) * 64 * AT;                            \
        float* sVb = sm + SV_OFF + (buf) * 64 * AT;                            \
        float* sPb = sm + SP_OFF + (buf) * 128 * AT;                           \
        const float* Kt = Kg + (size_t)(kt) * 64 * DK;                         \
        const float* Vt = Vg + (size_t)(kt) * 64 * DK;                         \
        const float* Bt = Bg + (kt) * 64;                                      \
        _Pragma("unroll")                                                      \
        for (int t = 0; t < 4; t++) {                                          \
            int cch = t * 256 + tid;                                           \
            int row = cch >> 4, col = (cch & 15) << 2;                         \
            cp16(&sKb[row * AT + col], Kt + row * DK + col);                   \
            cp16(&sVb[row * AT + col], Vt + row * DK + col);                   \
        }                                                                      \
        _Pragma("unroll")                                                      \
        for (int t = 0; t < 8; t++) {                                          \
            int cch = t * 256 + tid;                                           \
            int row = cch >> 4, col = (cch & 15) << 2;                         \
            cp16(&sPb[row * AT + col], Bt + (size_t)row * SEQ + col);          \
        }                                                                      \
    } while (0)

    {
#pragma unroll
        for (int t = 0; t < 8; t++) {
            int cch = t * 256 + tid;
            int row = cch >> 4, col = (cch & 15) << 2;
            cp16(&sm[SQ_OFF + row * AT + col], Qg + (size_t)row * DK + col);
        }
        cp16(&sMsk[tid * 4], maskW + (size_t)b * SEQ + tid * 4);
        ATTN_STAGE(0, 0);
        CP_COMMIT();
    }

    float mI[4], lI[4];
#pragma unroll
    for (int r = 0; r < 4; r++) { mI[r] = -INFINITY; lI[r] = 0.0f; }
    float o[2][4][4];
#pragma unroll
    for (int i = 0; i < 2; i++)
#pragma unroll
        for (int j = 0; j < 4; j++)
#pragma unroll
            for (int r = 0; r < 4; r++) o[i][j][r] = 0.0f;

    for (int kt = 0; kt < SEQ / 64; kt++) {
        const int buf = kt & 1;
        const int k0c = kt * 64;
        float* sKb = sm + SK_OFF + buf * 64 * AT;
        float* sVb = sm + SV_OFF + buf * 64 * AT;
        float* sPb = sm + SP_OFF + buf * 128 * AT;

        if (kt + 1 < SEQ / 64) ATTN_STAGE(buf ^ 1, kt + 1);
        CP_COMMIT();
        CP_WAIT1();
        __syncthreads();

        float c[2][4][4];
#pragma unroll
        for (int i = 0; i < 2; i++)
#pragma unroll
            for (int j = 0; j < 4; j++)
#pragma unroll
                for (int r = 0; r < 4; r++) c[i][j][r] = 0.0f;

#pragma unroll
        for (int kb = 0; kb < 64; kb += 8) {
            float2 qa[2][2];
            qa[0][0] = *(float2*)&sm[SQ_OFF + rr[0] * AT + kb + 2 * tig];
            qa[0][1] = *(float2*)&sm[SQ_OFF + rr[1] * AT + kb + 2 * tig];
            qa[1][0] = *(float2*)&sm[SQ_OFF + rr[2] * AT + kb + 2 * tig];
            qa[1][1] = *(float2*)&sm[SQ_OFF + rr[3] * AT + kb + 2 * tig];
#pragma unroll
            for (int j = 0; j < 4; j++) {
                int key = wn * 32 + j * 8 + gid;
                float2 kf = *(float2*)&sKb[key * AT + kb + 2 * tig];
                unsigned int b0 = __float_as_uint(kf.x);
                unsigned int b1 = __float_as_uint(kf.y);
#pragma unroll
                for (int i = 0; i < 2; i++)
                    mma_tf32(c[i][j],
                             __float_as_uint(qa[i][0].x), __float_as_uint(qa[i][1].x),
                             __float_as_uint(qa[i][0].y), __float_as_uint(qa[i][1].y),
                             b0, b1);
            }
        }

        float pm[4] = {-INFINITY, -INFINITY, -INFINITY, -INFINITY};
#pragma unroll
        for (int i = 0; i < 2; i++) {
#pragma unroll
            for (int j = 0; j < 4; j++) {
                int cc0 = wn * 32 + j * 8 + 2 * tig;
                int cc1 = cc0 + 1;
                bool mk0 = sMsk[k0c + cc0] != 0u;
                bool mk1 = sMsk[k0c + cc1] != 0u;
                float v0 = mk0 ? fmaf(c[i][j][0], scale, sPb[rr[2*i]   * AT + cc0]) : -10000.0f;
                float v1 = mk1 ? fmaf(c[i][j][1], scale, sPb[rr[2*i]   * AT + cc1]) : -10000.0f;
                float v2 = mk0 ? fmaf(c[i][j][2], scale, sPb[rr[2*i+1] * AT + cc0]) : -10000.0f;
                float v3 = mk1 ? fmaf(c[i][j][3], scale, sPb[rr[2*i+1] * AT + cc1]) : -10000.0f;
                c[i][j][0] = v0; c[i][j][1] = v1; c[i][j][2] = v2; c[i][j][3] = v3;
                pm[2*i]   = fmaxf(pm[2*i],   fmaxf(v0, v1));
                pm[2*i+1] = fmaxf(pm[2*i+1], fmaxf(v2, v3));
            }
        }
#pragma unroll
        for (int r = 0; r < 4; r++) {
            pm[r] = fmaxf(pm[r], __shfl_xor_sync(0xffffffffu, pm[r], 1));
            pm[r] = fmaxf(pm[r], __shfl_xor_sync(0xffffffffu, pm[r], 2));
        }
        if (tig == 0) {
#pragma unroll
            for (int r = 0; r < 4; r++) sMax[rr[r] * 2 + wn] = pm[r];
        }
        __syncthreads();

        float mN[4], al[4], ps[4];
#pragma unroll
        for (int r = 0; r < 4; r++) {
            mN[r] = fmaxf(mI[r], fmaxf(sMax[rr[r] * 2], sMax[rr[r] * 2 + 1]));
            al[r] = __expf(mI[r] - mN[r]);
            mI[r] = mN[r];
            ps[r] = 0.0f;
        }

#pragma unroll
        for (int i = 0; i < 2; i++) {
#pragma unroll
            for (int j = 0; j < 4; j++) {
                int base0 = rr[2*i]     * AT + wn * 32 + j * 8;
                int base1 = rr[2*i + 1] * AT + wn * 32 + j * 8;
                float p0 = __expf(c[i][j][0] - mN[2*i]);
                float p1 = __expf(c[i][j][1] - mN[2*i]);
                float p2 = __expf(c[i][j][2] - mN[2*i+1]);
                float p3 = __expf(c[i][j][3] - mN[2*i+1]);
                sPb[base0 + pu0] = tf32f(p0);
                sPb[base0 + pu1] = tf32f(p1);
                sPb[base1 + pu0] = tf32f(p2);
                sPb[base1 + pu1] = tf32f(p3);
                ps[2*i]   += p0 + p1;
                ps[2*i+1] += p2 + p3;
            }
        }
#pragma unroll
        for (int r = 0; r < 4; r++) {
            ps[r] += __shfl_xor_sync(0xffffffffu, ps[r], 1);
            ps[r] += __shfl_xor_sync(0xffffffffu, ps[r], 2);
        }
        if (tig == 0) {
#pragma unroll
            for (int r = 0; r < 4; r++) sSum[rr[r] * 2 + wn] = ps[r];
        }

#pragma unroll
        for (int i = 0; i < 2; i++)
#pragma unroll
            for (int j = 0; j < 4; j++) {
                o[i][j][0] *= al[2*i];   o[i][j][1] *= al[2*i];
                o[i][j][2] *= al[2*i+1]; o[i][j][3] *= al[2*i+1];
            }
        __syncthreads();

#pragma unroll
        for (int r = 0; r < 4; r++)
            lI[r] = lI[r] * al[r] + sSum[rr[r] * 2] + sSum[rr[r] * 2 + 1];

#pragma unroll
        for (int kb = 0; kb < 64; kb += 8) {
            float2 pa[2][2];
            pa[0][0] = *(float2*)&sPb[rr[0] * AT + kb + 2 * tig];
            pa[0][1] = *(float2*)&sPb[rr[1] * AT + kb + 2 * tig];
            pa[1][0] = *(float2*)&sPb[rr[2] * AT + kb + 2 * tig];
            pa[1][1] = *(float2*)&sPb[rr[3] * AT + kb + 2 * tig];
#pragma unroll
            for (int j = 0; j < 4; j++) {
                int dcol = wn * 32 + j * 8 + pg;
                unsigned int b0 = __float_as_uint(sVb[(kb + tig)     * AT + dcol]);
                unsigned int b1 = __float_as_uint(sVb[(kb + tig + 4) * AT + dcol]);
#pragma unroll
                for (int i = 0; i < 2; i++)
                    mma_tf32(o[i][j],
                             __float_as_uint(pa[i][0].x), __float_as_uint(pa[i][1].x),
                             __float_as_uint(pa[i][0].y), __float_as_uint(pa[i][1].y),
                             b0, b1);
            }
        }
        __syncthreads();
    }
#undef ATTN_STAGE

    float inv[4];
#pragma unroll
    for (int r = 0; r < 4; r++) inv[r] = 1.0f / lI[r];
    float* Og = g_O + ((size_t)b * SEQ + q0) * DMODEL + h * DK;
#pragma unroll
    for (int i = 0; i < 2; i++) {
#pragma unroll
        for (int j = 0; j < 4; j++) {
#pragma unroll
            for (int e = 0; e < 2; e++) {
                int cc = wn * 32 + j * 8 + 2 * tig + e;
                Og[(size_t)rr[2*i]     * DMODEL + cc] = tf32f(o[i][j][e]     * inv[2*i]);
                Og[(size_t)rr[2*i + 1] * DMODEL + cc] = tf32f(o[i][j][e + 2] * inv[2*i+1]);
            }
        }
    }
}

// ---------------------------------------------------------------------------
extern "C" void kernel_launch(void* const* d_in, const int* in_sizes, int n_in,
                              void* d_out, int out_size)
{
    // Identify inputs by element count (robust to metadata ordering)
    const float* X = 0; const float* Bij = 0; const void* maskP = 0;
    const float* Ws[4] = {0, 0, 0, 0};
    const float* bs[4] = {0, 0, 0, 0};
    int nW = 0, nB = 0;
    for (int i = 0; i < n_in; i++) {
        int sz = in_sizes[i];
        if (sz == BATCH * HEADS * SEQ * SEQ)      Bij  = (const float*)d_in[i];
        else if (sz == BATCH * SEQ * DMODEL)      X    = (const float*)d_in[i];
        else if (sz == BATCH * SEQ)               maskP = d_in[i];
        else if (sz == DMODEL * DMODEL && nW < 4) Ws[nW++] = (const float*)d_in[i];
        else if (sz == DMODEL && nB < 4)          bs[nB++] = (const float*)d_in[i];
    }
    const float *Wq = Ws[0], *Wk = Ws[1], *Wv = Ws[2], *Wo = Ws[3];
    const float *bq = bs[0], *bk = bs[1], *bv = bs[2], *bo = bs[3];
    float* out = (float*)d_out;

    float *op, *xr, *wr;
    cudaGetSymbolAddress((void**)&op, g_O);
    cudaGetSymbolAddress((void**)&xr, g_Xr);
    cudaGetSymbolAddress((void**)&wr, g_Wr);

    cudaFuncSetAttribute(attn_tc3_kernel, cudaFuncAttributeMaxDynamicSharedMemorySize,
                         ATTN_SMEM_BYTES);
    cudaFuncSetAttribute(tf32_gemm3_kernel, cudaFuncAttributeMaxDynamicSharedMemorySize,
                         GEMM_SMEM_BYTES);

    // Pre-round X and weights to tf32
    round_x_kernel<<<4096, 256>>>(X);
    round_w_kernel<<<4096, 256>>>(Wq, Wk, Wv, Wo);

    const int WSZ = DMODEL * DMODEL;

    // Fused QKV: grid.z = 3 selects W/bias/destination
    dim3 gQKV(DMODEL / TBN, (BATCH * SEQ) / TBM, 3);   // (8, 32, 3)
    tf32_gemm3_kernel<<<gQKV, 256, GEMM_SMEM_BYTES>>>(xr, wr, bq, bk, bv, 0, 1);

    dim3 gAttn(SEQ / 128, HEADS, BATCH);               // (8, 16, 4)
    attn_tc3_kernel<<<gAttn, 256, ATTN_SMEM_BYTES>>>(Bij, (const unsigned int*)maskP);

    // Output projection (z=0 only)
    dim3 gO(DMODEL / TBN, (BATCH * SEQ) / TBM, 1);
    tf32_gemm3_kernel<<<gO, 256, GEMM_SMEM_BYTES>>>(op, wr + 3 * WSZ, bo, bo, bo, out, 0);
}